// round 2
// baseline (speedup 1.0000x reference)
#include <cuda_runtime.h>
#include <math.h>

#define BATCHN 8
#define NHEAD 12
#define BH 96            // BATCHN*NHEAD
#define SEQ 4096
#define HD 64
#define NL 64            // landmarks
#define SEG 64           // SEQ / NL
#define NSPLIT 8
#define SPLEN 512        // SEQ / NSPLIT
#define TS 64            // tile along sequence
#define SCALE 0.35355339059327373f   // 64^(-1/4)
#define NEGBIG 1000000000.0f
#define PITCH 65

// -------- scratch (static device allocations; allowed) --------
__device__ float g_Ql[BH*NL*HD];
__device__ float g_Kl[BH*NL*HD];
__device__ float g_K2[BH*NL*NL];
__device__ float g_colmax[BH];
__device__ float g_Inv[BH*NL*NL];
__device__ float g_pacc[BH*NSPLIT*NL*HD];
__device__ float g_pm[BH*NSPLIT*NL];
__device__ float g_pd[BH*NSPLIT*NL];
__device__ float g_T3V[BH*NL*HD];
__device__ float g_W[BH*NL*HD];

// ================= K1: landmarks =================
// Q_l[bh][l][d] = mean over seg of Q*mask*scale ; same for K.
__global__ void k_landmarks(const float* __restrict__ Q,
                            const float* __restrict__ K,
                            const float* __restrict__ mask) {
    int bh = blockIdx.y;
    int l  = blockIdx.x;
    int d  = threadIdx.x;
    int b  = bh / NHEAD;
    const float* qb = Q + ((size_t)bh*SEQ + l*SEG)*HD;
    const float* kb = K + ((size_t)bh*SEQ + l*SEG)*HD;
    const float* mr = mask + (size_t)b*SEQ + l*SEG;
    float sq = 0.f, sk = 0.f;
    #pragma unroll 8
    for (int r = 0; r < SEG; r++) {
        float m = mr[r];
        sq += qb[r*HD + d] * m;
        sk += kb[r*HD + d] * m;
    }
    float c = SCALE / (float)SEG;
    g_Ql[(bh*NL + l)*HD + d] = sq * c;
    g_Kl[(bh*NL + l)*HD + d] = sk * c;
}

// ================= K2a: kernel_2 = softmax(Q_l K_l^T) + colsum max =================
__global__ void k_kernel2(void) {
    int bh = blockIdx.x;
    int t  = threadIdx.x;   // 64 threads
    __shared__ float sQ[NL*PITCH];
    __shared__ float sK[NL*PITCH];
    __shared__ float sP[NL*PITCH];
    __shared__ float red[NL];
    for (int r = 0; r < NL; r++) {
        sQ[r*PITCH + t] = g_Ql[(bh*NL + r)*HD + t];
        sK[r*PITCH + t] = g_Kl[(bh*NL + r)*HD + t];
    }
    __syncthreads();
    int l = t;
    float mx = -1e30f;
    for (int m = 0; m < NL; m++) {
        float s = 0.f;
        #pragma unroll 8
        for (int k = 0; k < HD; k++) s += sQ[l*PITCH + k] * sK[m*PITCH + k];
        sP[l*PITCH + m] = s;
        mx = fmaxf(mx, s);
    }
    float sum = 0.f;
    for (int m = 0; m < NL; m++) {
        float e = __expf(sP[l*PITCH + m] - mx);
        sP[l*PITCH + m] = e;
        sum += e;
    }
    float inv = 1.f / sum;
    for (int m = 0; m < NL; m++) {
        float v = sP[l*PITCH + m] * inv;
        sP[l*PITCH + m] = v;
        g_K2[(bh*NL + l)*NL + m] = v;
    }
    __syncthreads();
    // column sums (thread t = column)
    float cs = 0.f;
    for (int r = 0; r < NL; r++) cs += sP[r*PITCH + t];
    red[t] = cs;
    __syncthreads();
    for (int s = 32; s > 0; s >>= 1) {
        if (t < s) red[t] = fmaxf(red[t], red[t + s]);
        __syncthreads();
    }
    if (t == 0) g_colmax[bh] = red[0];
}

// ================= 64x64 shared matmul: C = alpha * A @ (beta*I + gamma*B) =================
__device__ __forceinline__ void mm64(float* C, const float* A, const float* B,
                                     float beta, float gamma, float alpha, int tid) {
    int i0 = (tid >> 4) << 2;
    int j0 = (tid & 15) << 2;
    float acc[4][4];
    #pragma unroll
    for (int u = 0; u < 4; u++)
        #pragma unroll
        for (int v = 0; v < 4; v++) acc[u][v] = 0.f;
    for (int k = 0; k < HD; k++) {
        float a[4], b[4];
        #pragma unroll
        for (int u = 0; u < 4; u++) a[u] = A[(i0+u)*PITCH + k];
        #pragma unroll
        for (int v = 0; v < 4; v++) {
            float x = B[k*PITCH + j0 + v];
            b[v] = gamma * x + ((k == j0 + v) ? beta : 0.f);
        }
        #pragma unroll
        for (int u = 0; u < 4; u++)
            #pragma unroll
            for (int v = 0; v < 4; v++) acc[u][v] += a[u] * b[v];
    }
    __syncthreads();   // all reads of C's previous role done
    #pragma unroll
    for (int u = 0; u < 4; u++)
        #pragma unroll
        for (int v = 0; v < 4; v++) C[(i0+u)*PITCH + j0 + v] = alpha * acc[u][v];
    __syncthreads();
}

// ================= K2b: Newton-Schulz pinv, 6 iters =================
__global__ void k_inv(void) {
    extern __shared__ float sm[];
    float* Km = sm;
    float* Vb = sm + 1*NL*PITCH;
    float* Pb = sm + 2*NL*PITCH;
    float* T1 = sm + 3*NL*PITCH;
    float* T2 = sm + 4*NL*PITCH;
    int bh = blockIdx.x;
    int tid = threadIdx.x;  // 256
    for (int e = tid; e < NL*NL; e += 256) {
        int r = e >> 6, c = e & 63;
        Km[r*PITCH + c] = g_K2[bh*NL*NL + e];
    }
    float gmax = -1e30f;
    for (int i = 0; i < BH; i++) gmax = fmaxf(gmax, g_colmax[i]);
    float ig = 1.f / gmax;
    __syncthreads();
    for (int e = tid; e < NL*NL; e += 256) {
        int r = e >> 6, c = e & 63;
        Vb[r*PITCH + c] = Km[c*PITCH + r] * ig;   // transpose / gmax
    }
    __syncthreads();
    float *Vp = Vb, *T1p = T1;
    for (int it = 0; it < 6; it++) {
        mm64(Pb,  Km, Vp,  0.f,  1.f, 1.f,   tid);   // KV = Km @ V
        mm64(T1p, Pb, Pb,  7.f, -1.f, 1.f,   tid);   // T1 = KV @ (7I - KV)
        mm64(T2,  Pb, T1p, 15.f, -1.f, 1.f,  tid);   // T2 = KV @ (15I - T1)
        mm64(T1p, Vp, T2,  13.f, -1.f, 0.25f, tid);  // Vnew = 0.25 V @ (13I - T2)
        float* t = Vp; Vp = T1p; T1p = t;
    }
    for (int e = tid; e < NL*NL; e += 256) {
        int r = e >> 6, c = e & 63;
        g_Inv[bh*NL*NL + e] = Vp[r*PITCH + c];
    }
}

// ================= K3: flash-style kernel_3 @ V, split over S =================
__global__ void k_flash3(const float* __restrict__ K,
                         const float* __restrict__ V,
                         const float* __restrict__ mask) {
    extern __shared__ float sm[];
    float* sQ = sm;
    float* sK = sm + 1*NL*PITCH;
    float* sV = sm + 2*NL*PITCH;
    float* sP = sm + 3*NL*PITCH;
    __shared__ float ms[NL], ds[NL], rs[NL], bias[TS];
    int bh = blockIdx.y;
    int sp = blockIdx.x;
    int b  = bh / NHEAD;
    int tid = threadIdx.x;  // 256
    int i0 = (tid >> 4) << 2;
    int j0 = (tid & 15) << 2;

    for (int e = tid; e < NL*HD; e += 256) {
        int r = e >> 6, c = e & 63;
        sQ[r*PITCH + c] = g_Ql[bh*NL*HD + e];
    }
    if (tid < NL) { ms[tid] = -1e30f; ds[tid] = 0.f; }
    float acc[4][4];
    #pragma unroll
    for (int u = 0; u < 4; u++)
        #pragma unroll
        for (int v = 0; v < 4; v++) acc[u][v] = 0.f;
    __syncthreads();

    for (int t = 0; t < SPLEN/TS; t++) {
        int s0 = sp*SPLEN + t*TS;
        for (int e = tid; e < TS*HD; e += 256) {
            int r = e >> 6, c = e & 63;
            int s = s0 + r;
            float mk = mask[(size_t)b*SEQ + s];
            sK[r*PITCH + c] = K[((size_t)bh*SEQ + s)*HD + c] * mk * SCALE;
            sV[r*PITCH + c] = V[((size_t)bh*SEQ + s)*HD + c];
        }
        if (tid < TS) bias[tid] = -NEGBIG * (1.f - mask[(size_t)b*SEQ + s0 + tid]);
        __syncthreads();
        // logits p[i][j] = Ql[i] . Ks[j]
        float p[4][4];
        #pragma unroll
        for (int u = 0; u < 4; u++)
            #pragma unroll
            for (int v = 0; v < 4; v++) p[u][v] = 0.f;
        for (int k = 0; k < HD; k++) {
            float a[4], bb[4];
            #pragma unroll
            for (int u = 0; u < 4; u++) a[u] = sQ[(i0+u)*PITCH + k];
            #pragma unroll
            for (int v = 0; v < 4; v++) bb[v] = sK[(j0+v)*PITCH + k];
            #pragma unroll
            for (int u = 0; u < 4; u++)
                #pragma unroll
                for (int v = 0; v < 4; v++) p[u][v] += a[u] * bb[v];
        }
        #pragma unroll
        for (int u = 0; u < 4; u++)
            #pragma unroll
            for (int v = 0; v < 4; v++) sP[(i0+u)*PITCH + j0 + v] = p[u][v] + bias[j0+v];
        __syncthreads();
        // online softmax per row
        if (tid < NL) {
            int i = tid;
            float mloc = -1e30f;
            for (int j = 0; j < TS; j++) mloc = fmaxf(mloc, sP[i*PITCH + j]);
            float mnew = fmaxf(ms[i], mloc);
            float r_ = __expf(ms[i] - mnew);
            float s = 0.f;
            for (int j = 0; j < TS; j++) {
                float e = __expf(sP[i*PITCH + j] - mnew);
                sP[i*PITCH + j] = e;
                s += e;
            }
            ds[i] = ds[i]*r_ + s;
            ms[i] = mnew;
            rs[i] = r_;
        }
        __syncthreads();
        // acc = acc * r + P @ V
        float f[4];
        #pragma unroll
        for (int u = 0; u < 4; u++) f[u] = rs[i0+u];
        #pragma unroll
        for (int u = 0; u < 4; u++)
            #pragma unroll
            for (int v = 0; v < 4; v++) acc[u][v] *= f[u];
        for (int k = 0; k < TS; k++) {
            float a[4], bb[4];
            #pragma unroll
            for (int u = 0; u < 4; u++) a[u] = sP[(i0+u)*PITCH + k];
            #pragma unroll
            for (int v = 0; v < 4; v++) bb[v] = sV[k*PITCH + j0 + v];
            #pragma unroll
            for (int u = 0; u < 4; u++)
                #pragma unroll
                for (int v = 0; v < 4; v++) acc[u][v] += a[u] * bb[v];
        }
        __syncthreads();
    }
    // write partials (unnormalized, relative to ms)
    size_t base = ((size_t)bh*NSPLIT + sp)*NL;
    #pragma unroll
    for (int u = 0; u < 4; u++)
        #pragma unroll
        for (int v = 0; v < 4; v++)
            g_pacc[(base + i0 + u)*HD + j0 + v] = acc[u][v];
    if (tid < NL) {
        g_pm[base + tid] = ms[tid];
        g_pd[base + tid] = ds[tid];
    }
}

// ================= K3m: merge split partials -> T3V =================
__global__ void k_merge(void) {
    int bh = blockIdx.x;
    int tid = threadIdx.x;  // 256
    __shared__ float esc[NSPLIT][NL];
    if (tid < NL) {
        int i = tid;
        float M = -1e30f;
        for (int s = 0; s < NSPLIT; s++) M = fmaxf(M, g_pm[((size_t)bh*NSPLIT + s)*NL + i]);
        float Dsum = 0.f;
        for (int s = 0; s < NSPLIT; s++)
            Dsum += g_pd[((size_t)bh*NSPLIT + s)*NL + i] *
                    __expf(g_pm[((size_t)bh*NSPLIT + s)*NL + i] - M);
        float invD = 1.f / Dsum;
        for (int s = 0; s < NSPLIT; s++)
            esc[s][i] = __expf(g_pm[((size_t)bh*NSPLIT + s)*NL + i] - M) * invD;
    }
    __syncthreads();
    for (int e = tid; e < NL*HD; e += 256) {
        int i = e >> 6;
        float acc = 0.f;
        #pragma unroll
        for (int s = 0; s < NSPLIT; s++)
            acc += g_pacc[(((size_t)bh*NSPLIT + s)*NL)*HD + e] * esc[s][i];
        g_T3V[(size_t)bh*NL*HD + e] = acc;
    }
}

// ================= K4: W = Inv @ T3V =================
__global__ void k_wmat(void) {
    __shared__ float A[NL*PITCH];
    __shared__ float Bm[NL*PITCH];
    int bh = blockIdx.x;
    int tid = threadIdx.x;  // 256
    for (int e = tid; e < NL*NL; e += 256) {
        int r = e >> 6, c = e & 63;
        A[r*PITCH + c]  = g_Inv[bh*NL*NL + e];
        Bm[r*PITCH + c] = g_T3V[bh*NL*HD + e];
    }
    __syncthreads();
    int i0 = (tid >> 4) << 2;
    int j0 = (tid & 15) << 2;
    float acc[4][4];
    #pragma unroll
    for (int u = 0; u < 4; u++)
        #pragma unroll
        for (int v = 0; v < 4; v++) acc[u][v] = 0.f;
    for (int k = 0; k < NL; k++) {
        float a[4], b[4];
        #pragma unroll
        for (int u = 0; u < 4; u++) a[u] = A[(i0+u)*PITCH + k];
        #pragma unroll
        for (int v = 0; v < 4; v++) b[v] = Bm[k*PITCH + j0 + v];
        #pragma unroll
        for (int u = 0; u < 4; u++)
            #pragma unroll
            for (int v = 0; v < 4; v++) acc[u][v] += a[u] * b[v];
    }
    #pragma unroll
    for (int u = 0; u < 4; u++)
        #pragma unroll
        for (int v = 0; v < 4; v++)
            g_W[((size_t)bh*NL + i0 + u)*HD + j0 + v] = acc[u][v];
}

// ================= K5: X = softmax(Qs K_l^T) @ W =================
__global__ void k_final(const float* __restrict__ Q,
                        const float* __restrict__ mask,
                        float* __restrict__ out) {
    extern __shared__ float sm[];
    float* sQ  = sm;
    float* sKl = sm + 1*NL*PITCH;
    float* sW  = sm + 2*NL*PITCH;
    float* sP  = sm + 3*NL*PITCH;
    int bh = blockIdx.y;
    int st = blockIdx.x;
    int b  = bh / NHEAD;
    int s0 = st * TS;
    int tid = threadIdx.x;  // 256
    int i0 = (tid >> 4) << 2;
    int j0 = (tid & 15) << 2;

    for (int e = tid; e < NL*HD; e += 256) {
        int r = e >> 6, c = e & 63;
        sKl[r*PITCH + c] = g_Kl[(size_t)bh*NL*HD + e];
        sW[r*PITCH + c]  = g_W[(size_t)bh*NL*HD + e];
        int s = s0 + r;
        float mk = mask[(size_t)b*SEQ + s];
        sQ[r*PITCH + c] = Q[((size_t)bh*SEQ + s)*HD + c] * mk * SCALE;
    }
    __syncthreads();
    // logits
    float p[4][4];
    #pragma unroll
    for (int u = 0; u < 4; u++)
        #pragma unroll
        for (int v = 0; v < 4; v++) p[u][v] = 0.f;
    for (int k = 0; k < HD; k++) {
        float a[4], bb[4];
        #pragma unroll
        for (int u = 0; u < 4; u++) a[u] = sQ[(i0+u)*PITCH + k];
        #pragma unroll
        for (int v = 0; v < 4; v++) bb[v] = sKl[(j0+v)*PITCH + k];
        #pragma unroll
        for (int u = 0; u < 4; u++)
            #pragma unroll
            for (int v = 0; v < 4; v++) p[u][v] += a[u] * bb[v];
    }
    #pragma unroll
    for (int u = 0; u < 4; u++)
        #pragma unroll
        for (int v = 0; v < 4; v++) sP[(i0+u)*PITCH + j0 + v] = p[u][v];
    __syncthreads();
    // row softmax over 64 landmarks
    if (tid < TS) {
        int i = tid;
        float mx = -1e30f;
        for (int l = 0; l < NL; l++) mx = fmaxf(mx, sP[i*PITCH + l]);
        float s = 0.f;
        for (int l = 0; l < NL; l++) {
            float e = __expf(sP[i*PITCH + l] - mx);
            sP[i*PITCH + l] = e;
            s += e;
        }
        float inv = 1.f / s;
        for (int l = 0; l < NL; l++) sP[i*PITCH + l] *= inv;
    }
    __syncthreads();
    // out = P @ W
    float o[4][4];
    #pragma unroll
    for (int u = 0; u < 4; u++)
        #pragma unroll
        for (int v = 0; v < 4; v++) o[u][v] = 0.f;
    for (int l = 0; l < NL; l++) {
        float a[4], b[4];
        #pragma unroll
        for (int u = 0; u < 4; u++) a[u] = sP[(i0+u)*PITCH + l];
        #pragma unroll
        for (int v = 0; v < 4; v++) b[v] = sW[l*PITCH + j0 + v];
        #pragma unroll
        for (int u = 0; u < 4; u++)
            #pragma unroll
            for (int v = 0; v < 4; v++) o[u][v] += a[u] * b[v];
    }
    #pragma unroll
    for (int u = 0; u < 4; u++) {
        size_t row = ((size_t)bh*SEQ + s0 + i0 + u)*HD + j0;
        float4 w = make_float4(o[u][0], o[u][1], o[u][2], o[u][3]);
        *reinterpret_cast<float4*>(out + row) = w;
    }
}

// ================= launch =================
extern "C" void kernel_launch(void* const* d_in, const int* in_sizes, int n_in,
                              void* d_out, int out_size) {
    const float* Q    = (const float*)d_in[0];
    const float* K    = (const float*)d_in[1];
    const float* V    = (const float*)d_in[2];
    const float* mask = (const float*)d_in[3];
    float* out = (float*)d_out;

    const int SMEM_INV = 5 * NL * PITCH * sizeof(float);    // 83200
    const int SMEM_BIG = 4 * NL * PITCH * sizeof(float);    // 66560
    cudaFuncSetAttribute(k_inv,    cudaFuncAttributeMaxDynamicSharedMemorySize, SMEM_INV);
    cudaFuncSetAttribute(k_flash3, cudaFuncAttributeMaxDynamicSharedMemorySize, SMEM_BIG);
    cudaFuncSetAttribute(k_final,  cudaFuncAttributeMaxDynamicSharedMemorySize, SMEM_BIG);

    k_landmarks<<<dim3(NL, BH), HD>>>(Q, K, mask);
    k_kernel2<<<BH, NL>>>();
    k_inv<<<BH, 256, SMEM_INV>>>();
    k_flash3<<<dim3(NSPLIT, BH), 256, SMEM_BIG>>>(K, V, mask);
    k_merge<<<BH, 256>>>();
    k_wmat<<<BH, 256>>>();
    k_final<<<dim3(SEQ/TS, BH), 256, SMEM_BIG>>>(Q, mask, out);
}

// round 3
// speedup vs baseline: 1.4748x; 1.4748x over previous
#include <cuda_runtime.h>
#include <math.h>
#include <stdint.h>

#define BATCHN 8
#define NHEAD 12
#define BH 96            // BATCHN*NHEAD
#define SEQ 4096
#define HD 64
#define NL 64            // landmarks
#define SEG 64           // SEQ / NL
#define NSPLIT 8
#define SPLEN 512        // SEQ / NSPLIT
#define TS 64
#define NTF 4            // seq tiles per k_final block
#define SCALE 0.35355339059327373f   // 64^(-1/4)
#define NEGBIG 1000000000.0f
#define PA 68            // pitch for A-side / n-row-indexed buffers (== 4 mod 32)
#define PB 72            // pitch for k-row-indexed buffers (== 8 mod 32)
#define P2 65            // pitch for k_kernel2 (old SIMT pattern)

// -------- scratch --------
__device__ float g_Ql[BH*NL*HD];
__device__ float g_Kl[BH*NL*HD];
__device__ float g_K2[BH*NL*NL];
__device__ float g_colmax[BH];
__device__ float g_Inv[BH*NL*NL];
__device__ float g_pacc[BH*NSPLIT*NL*HD];
__device__ float g_pd[BH*NSPLIT*NL];
__device__ float g_W[BH*NL*HD];

__device__ __forceinline__ float tf32r(float x){
    uint32_t u; asm("cvt.rna.tf32.f32 %0, %1;" : "=r"(u) : "f"(x));
    return __uint_as_float(u);
}
__device__ __forceinline__ void mma8(float c[4],
                                     uint32_t a0,uint32_t a1,uint32_t a2,uint32_t a3,
                                     uint32_t b0,uint32_t b1){
    asm volatile("mma.sync.aligned.m16n8k8.row.col.f32.tf32.tf32.f32 "
        "{%0,%1,%2,%3}, {%4,%5,%6,%7}, {%8,%9}, {%0,%1,%2,%3};"
        : "+f"(c[0]),"+f"(c[1]),"+f"(c[2]),"+f"(c[3])
        : "r"(a0),"r"(a1),"r"(a2),"r"(a3),"r"(b0),"r"(b1));
}

// ================= K1: landmarks =================
__global__ void k_landmarks(const float* __restrict__ Q,
                            const float* __restrict__ K,
                            const float* __restrict__ mask) {
    int bh = blockIdx.y;
    int l  = blockIdx.x;
    int d  = threadIdx.x;
    int b  = bh / NHEAD;
    const float* qb = Q + ((size_t)bh*SEQ + l*SEG)*HD;
    const float* kb = K + ((size_t)bh*SEQ + l*SEG)*HD;
    const float* mr = mask + (size_t)b*SEQ + l*SEG;
    float sq = 0.f, sk = 0.f;
    #pragma unroll 8
    for (int r = 0; r < SEG; r++) {
        float m = mr[r];
        sq += qb[r*HD + d] * m;
        sk += kb[r*HD + d] * m;
    }
    float c = SCALE / (float)SEG;
    g_Ql[(bh*NL + l)*HD + d] = sq * c;
    g_Kl[(bh*NL + l)*HD + d] = sk * c;
}

// ================= K2a: kernel_2 softmax + colsum max =================
__global__ void k_kernel2(void) {
    int bh = blockIdx.x;
    int t  = threadIdx.x;   // 64 threads
    __shared__ float sQ[NL*P2];
    __shared__ float sK[NL*P2];
    __shared__ float sP[NL*P2];
    __shared__ float red[NL];
    for (int r = 0; r < NL; r++) {
        sQ[r*P2 + t] = g_Ql[(bh*NL + r)*HD + t];
        sK[r*P2 + t] = g_Kl[(bh*NL + r)*HD + t];
    }
    __syncthreads();
    int l = t;
    float mx = -1e30f;
    for (int m = 0; m < NL; m++) {
        float s = 0.f;
        #pragma unroll 8
        for (int k = 0; k < HD; k++) s += sQ[l*P2 + k] * sK[m*P2 + k];
        sP[l*P2 + m] = s;
        mx = fmaxf(mx, s);
    }
    float sum = 0.f;
    for (int m = 0; m < NL; m++) {
        float e = __expf(sP[l*P2 + m] - mx);
        sP[l*P2 + m] = e;
        sum += e;
    }
    float inv = 1.f / sum;
    for (int m = 0; m < NL; m++) {
        float v = sP[l*P2 + m] * inv;
        sP[l*P2 + m] = v;
        g_K2[(bh*NL + l)*NL + m] = v;
    }
    __syncthreads();
    float cs = 0.f;
    for (int r = 0; r < NL; r++) cs += sP[r*P2 + t];
    red[t] = cs;
    __syncthreads();
    for (int s = 32; s > 0; s >>= 1) {
        if (t < s) red[t] = fmaxf(red[t], red[t + s]);
        __syncthreads();
    }
    if (t == 0) g_colmax[bh] = red[0];
}

// ================= 64x64 SIMT matmul (pitch PB): C = alpha * A @ (beta*I + gamma*B) ==========
__device__ __forceinline__ void mm64(float* C, const float* A, const float* B,
                                     float beta, float gamma, float alpha, int tid) {
    int i0 = (tid >> 4) << 2;
    int j0 = (tid & 15) << 2;
    float acc[4][4];
    #pragma unroll
    for (int u = 0; u < 4; u++)
        #pragma unroll
        for (int v = 0; v < 4; v++) acc[u][v] = 0.f;
    for (int k = 0; k < HD; k++) {
        float a[4], b[4];
        #pragma unroll
        for (int u = 0; u < 4; u++) a[u] = A[(i0+u)*PB + k];
        #pragma unroll
        for (int v = 0; v < 4; v++) {
            float x = B[k*PB + j0 + v];
            b[v] = gamma * x + ((k == j0 + v) ? beta : 0.f);
        }
        #pragma unroll
        for (int u = 0; u < 4; u++)
            #pragma unroll
            for (int v = 0; v < 4; v++) acc[u][v] += a[u] * b[v];
    }
    __syncthreads();
    #pragma unroll
    for (int u = 0; u < 4; u++)
        #pragma unroll
        for (int v = 0; v < 4; v++) C[(i0+u)*PB + j0 + v] = alpha * acc[u][v];
    __syncthreads();
}

// ================= Newton-Schulz pinv body (fp32 SIMT) =================
__device__ void inv_body(float* sm) {
    float* Km = sm;
    float* Vb = sm + 1*NL*PB;
    float* Pb = sm + 2*NL*PB;
    float* T1 = sm + 3*NL*PB;
    float* T2 = sm + 4*NL*PB;
    int bh = blockIdx.y;
    int tid = threadIdx.x;
    for (int e = tid; e < NL*NL; e += 256) {
        int r = e >> 6, c = e & 63;
        Km[r*PB + c] = g_K2[bh*NL*NL + e];
    }
    float gmax = -1e30f;
    for (int i = 0; i < BH; i++) gmax = fmaxf(gmax, g_colmax[i]);
    float ig = 1.f / gmax;
    __syncthreads();
    for (int e = tid; e < NL*NL; e += 256) {
        int r = e >> 6, c = e & 63;
        Vb[r*PB + c] = Km[c*PB + r] * ig;
    }
    __syncthreads();
    float *Vp = Vb, *T1p = T1;
    for (int it = 0; it < 6; it++) {
        mm64(Pb,  Km, Vp,  0.f,  1.f, 1.f,   tid);
        mm64(T1p, Pb, Pb,  7.f, -1.f, 1.f,   tid);
        mm64(T2,  Pb, T1p, 15.f, -1.f, 1.f,  tid);
        mm64(T1p, Vp, T2,  13.f, -1.f, 0.25f, tid);
        float* t = Vp; Vp = T1p; T1p = t;
    }
    for (int e = tid; e < NL*NL; e += 256) {
        int r = e >> 6, c = e & 63;
        g_Inv[bh*NL*NL + e] = Vp[r*PB + c];
    }
}

// ================= flash kernel_3 @ V body (tf32 mma, no rescale) =================
__device__ void flash3_body(const float* __restrict__ K, const float* __restrict__ V,
                            const float* __restrict__ mask, float* sm) {
    float* sQ = sm;                    // 64 x PA
    float* sK = sm + NL*PA;            // 64 x PA
    float* sV = sm + 2*NL*PA;          // 64 x PB
    float* sP = sm + 2*NL*PA + NL*PB;  // 64 x PA
    __shared__ float sbias[TS];
    __shared__ float dred[NL][2];

    int bh = blockIdx.y, sp = blockIdx.x, b = bh / NHEAD;
    int tid = threadIdx.x, lane = tid & 31, warp = tid >> 5;
    int wr = warp & 3, wc = warp >> 2;
    int g = lane >> 2, t4 = lane & 3;
    int r0 = wr*16 + g, r1 = r0 + 8;

    for (int e = tid; e < NL*HD; e += 256) {
        int r = e >> 6, c = e & 63;
        sQ[r*PA + c] = tf32r(g_Ql[(size_t)bh*NL*HD + e]);
    }
    float o[4][4];
    #pragma unroll
    for (int nt = 0; nt < 4; nt++)
        #pragma unroll
        for (int j = 0; j < 4; j++) o[nt][j] = 0.f;
    float dp0 = 0.f, dp1 = 0.f;

    for (int tt = 0; tt < SPLEN/TS; tt++) {
        int s0 = sp*SPLEN + tt*TS;
        for (int e = tid; e < TS*HD; e += 256) {
            int r = e >> 6, c = e & 63;
            int s = s0 + r;
            float mk = mask[(size_t)b*SEQ + s];
            sK[r*PA + c] = tf32r(K[((size_t)bh*SEQ + s)*HD + c] * mk * SCALE);
            sV[r*PB + c] = tf32r(V[((size_t)bh*SEQ + s)*HD + c]);
        }
        if (tid < TS) sbias[tid] = -NEGBIG * (1.f - mask[(size_t)b*SEQ + s0 + tid]);
        __syncthreads();

        // S = Ql @ Ks^T
        float cf[4][4];
        #pragma unroll
        for (int nt = 0; nt < 4; nt++)
            #pragma unroll
            for (int j = 0; j < 4; j++) cf[nt][j] = 0.f;
        #pragma unroll
        for (int ks = 0; ks < 8; ks++) {
            int kb = ks*8 + t4;
            uint32_t a0 = __float_as_uint(sQ[r0*PA + kb]);
            uint32_t a1 = __float_as_uint(sQ[r1*PA + kb]);
            uint32_t a2 = __float_as_uint(sQ[r0*PA + kb + 4]);
            uint32_t a3 = __float_as_uint(sQ[r1*PA + kb + 4]);
            #pragma unroll
            for (int nt = 0; nt < 4; nt++) {
                int n = wc*32 + nt*8 + g;
                uint32_t b0 = __float_as_uint(sK[n*PA + kb]);
                uint32_t b1 = __float_as_uint(sK[n*PA + kb + 4]);
                mma8(cf[nt], a0, a1, a2, a3, b0, b1);
            }
        }
        // exp (+mask bias), accumulate row sums, stage P
        #pragma unroll
        for (int nt = 0; nt < 4; nt++) {
            int cb = wc*32 + nt*8 + t4*2;
            float bb0 = sbias[cb], bb1 = sbias[cb+1];
            float e0 = __expf(cf[nt][0] + bb0), e1 = __expf(cf[nt][1] + bb1);
            float e2 = __expf(cf[nt][2] + bb0), e3 = __expf(cf[nt][3] + bb1);
            dp0 += e0 + e1; dp1 += e2 + e3;
            *(float2*)&sP[r0*PA + cb] = make_float2(tf32r(e0), tf32r(e1));
            *(float2*)&sP[r1*PA + cb] = make_float2(tf32r(e2), tf32r(e3));
        }
        __syncthreads();
        // O += P @ V
        #pragma unroll
        for (int ks = 0; ks < 8; ks++) {
            int kb = ks*8 + t4;
            uint32_t a0 = __float_as_uint(sP[r0*PA + kb]);
            uint32_t a1 = __float_as_uint(sP[r1*PA + kb]);
            uint32_t a2 = __float_as_uint(sP[r0*PA + kb + 4]);
            uint32_t a3 = __float_as_uint(sP[r1*PA + kb + 4]);
            #pragma unroll
            for (int nt = 0; nt < 4; nt++) {
                int n = wc*32 + nt*8 + g;
                uint32_t b0 = __float_as_uint(sV[kb*PB + n]);
                uint32_t b1 = __float_as_uint(sV[(kb+4)*PB + n]);
                mma8(o[nt], a0, a1, a2, a3, b0, b1);
            }
        }
        __syncthreads();
    }
    // epilogue: unnormalized partials + row sums
    size_t base = ((size_t)bh*NSPLIT + sp)*NL;
    #pragma unroll
    for (int nt = 0; nt < 4; nt++) {
        int cb = wc*32 + nt*8 + t4*2;
        *(float2*)&g_pacc[(base + r0)*HD + cb] = make_float2(o[nt][0], o[nt][1]);
        *(float2*)&g_pacc[(base + r1)*HD + cb] = make_float2(o[nt][2], o[nt][3]);
    }
    dp0 += __shfl_xor_sync(0xffffffffu, dp0, 1);
    dp0 += __shfl_xor_sync(0xffffffffu, dp0, 2);
    dp1 += __shfl_xor_sync(0xffffffffu, dp1, 1);
    dp1 += __shfl_xor_sync(0xffffffffu, dp1, 2);
    if (t4 == 0) { dred[r0][wc] = dp0; dred[r1][wc] = dp1; }
    __syncthreads();
    if (tid < NL) g_pd[base + tid] = dred[tid][0] + dred[tid][1];
}

// ================= fused middle kernel: flash3 (x<8) || inv (x==8) =================
__global__ void __launch_bounds__(256) k_mid(const float* __restrict__ K,
                                             const float* __restrict__ V,
                                             const float* __restrict__ mask) {
    extern __shared__ float sm[];
    if (blockIdx.x < NSPLIT) flash3_body(K, V, mask, sm);
    else                     inv_body(sm);
}

// ================= merge partials + W = Inv @ T3V =================
__global__ void __launch_bounds__(256) k_mergewmat(void) {
    __shared__ float A[NL*PB];
    __shared__ float T[NL*PB];
    __shared__ float dtot[NL];
    int bh = blockIdx.x, tid = threadIdx.x;
    for (int e = tid; e < NL*NL; e += 256) {
        int r = e >> 6, c = e & 63;
        A[r*PB + c] = g_Inv[bh*NL*NL + e];
    }
    if (tid < NL) {
        float s = 0.f;
        #pragma unroll
        for (int k = 0; k < NSPLIT; k++) s += g_pd[((size_t)bh*NSPLIT + k)*NL + tid];
        dtot[tid] = s;
    }
    __syncthreads();
    for (int e = tid; e < NL*HD; e += 256) {
        int r = e >> 6, c = e & 63;
        float acc = 0.f;
        #pragma unroll
        for (int s = 0; s < NSPLIT; s++)
            acc += g_pacc[(((size_t)bh*NSPLIT + s)*NL)*HD + e];
        T[r*PB + c] = acc / dtot[r];
    }
    __syncthreads();
    int i0 = (tid >> 4) << 2;
    int j0 = (tid & 15) << 2;
    float acc[4][4];
    #pragma unroll
    for (int u = 0; u < 4; u++)
        #pragma unroll
        for (int v = 0; v < 4; v++) acc[u][v] = 0.f;
    for (int k = 0; k < NL; k++) {
        float a[4], b[4];
        #pragma unroll
        for (int u = 0; u < 4; u++) a[u] = A[(i0+u)*PB + k];
        #pragma unroll
        for (int v = 0; v < 4; v++) b[v] = T[k*PB + j0 + v];
        #pragma unroll
        for (int u = 0; u < 4; u++)
            #pragma unroll
            for (int v = 0; v < 4; v++) acc[u][v] += a[u] * b[v];
    }
    #pragma unroll
    for (int u = 0; u < 4; u++)
        #pragma unroll
        for (int v = 0; v < 4; v++)
            g_W[((size_t)bh*NL + i0 + u)*HD + j0 + v] = acc[u][v];
}

// ================= K5: X = softmax(Qs K_l^T) @ W  (tf32 mma) =================
__global__ void __launch_bounds__(256) k_final(const float* __restrict__ Q,
                                               const float* __restrict__ mask,
                                               float* __restrict__ out) {
    extern __shared__ float sm[];
    float* sKl = sm;                   // 64 x PA
    float* sQ  = sm + NL*PA;           // 64 x PA
    float* sP  = sm + 2*NL*PA;         // 64 x PA
    float* sW  = sm + 3*NL*PA;         // 64 x PB
    __shared__ float rsum[NL][2];

    int bh = blockIdx.y, b = bh / NHEAD;
    int tid = threadIdx.x, lane = tid & 31, warp = tid >> 5;
    int wr = warp & 3, wc = warp >> 2;
    int g = lane >> 2, t4 = lane & 3;
    int r0 = wr*16 + g, r1 = r0 + 8;

    for (int e = tid; e < NL*HD; e += 256) {
        int r = e >> 6, c = e & 63;
        sKl[r*PA + c] = tf32r(g_Kl[(size_t)bh*NL*HD + e]);
        sW[r*PB + c]  = tf32r(g_W[(size_t)bh*NL*HD + e]);
    }
    for (int tt = 0; tt < NTF; tt++) {
        int s0 = (blockIdx.x*NTF + tt)*TS;
        for (int e = tid; e < TS*HD; e += 256) {
            int r = e >> 6, c = e & 63;
            int s = s0 + r;
            float mk = mask[(size_t)b*SEQ + s];
            sQ[r*PA + c] = tf32r(Q[((size_t)bh*SEQ + s)*HD + c] * mk * SCALE);
        }
        __syncthreads();
        // S = Qs @ Kl^T
        float cf[4][4];
        #pragma unroll
        for (int nt = 0; nt < 4; nt++)
            #pragma unroll
            for (int j = 0; j < 4; j++) cf[nt][j] = 0.f;
        #pragma unroll
        for (int ks = 0; ks < 8; ks++) {
            int kb = ks*8 + t4;
            uint32_t a0 = __float_as_uint(sQ[r0*PA + kb]);
            uint32_t a1 = __float_as_uint(sQ[r1*PA + kb]);
            uint32_t a2 = __float_as_uint(sQ[r0*PA + kb + 4]);
            uint32_t a3 = __float_as_uint(sQ[r1*PA + kb + 4]);
            #pragma unroll
            for (int nt = 0; nt < 4; nt++) {
                int n = wc*32 + nt*8 + g;
                uint32_t b0 = __float_as_uint(sKl[n*PA + kb]);
                uint32_t b1 = __float_as_uint(sKl[n*PA + kb + 4]);
                mma8(cf[nt], a0, a1, a2, a3, b0, b1);
            }
        }
        float dp0 = 0.f, dp1 = 0.f;
        #pragma unroll
        for (int nt = 0; nt < 4; nt++) {
            int cb = wc*32 + nt*8 + t4*2;
            float e0 = __expf(cf[nt][0]), e1 = __expf(cf[nt][1]);
            float e2 = __expf(cf[nt][2]), e3 = __expf(cf[nt][3]);
            dp0 += e0 + e1; dp1 += e2 + e3;
            *(float2*)&sP[r0*PA + cb] = make_float2(tf32r(e0), tf32r(e1));
            *(float2*)&sP[r1*PA + cb] = make_float2(tf32r(e2), tf32r(e3));
        }
        dp0 += __shfl_xor_sync(0xffffffffu, dp0, 1);
        dp0 += __shfl_xor_sync(0xffffffffu, dp0, 2);
        dp1 += __shfl_xor_sync(0xffffffffu, dp1, 1);
        dp1 += __shfl_xor_sync(0xffffffffu, dp1, 2);
        if (t4 == 0) { rsum[r0][wc] = dp0; rsum[r1][wc] = dp1; }
        __syncthreads();
        // O = P @ W, then normalize rows
        float o[4][4];
        #pragma unroll
        for (int nt = 0; nt < 4; nt++)
            #pragma unroll
            for (int j = 0; j < 4; j++) o[nt][j] = 0.f;
        #pragma unroll
        for (int ks = 0; ks < 8; ks++) {
            int kb = ks*8 + t4;
            uint32_t a0 = __float_as_uint(sP[r0*PA + kb]);
            uint32_t a1 = __float_as_uint(sP[r1*PA + kb]);
            uint32_t a2 = __float_as_uint(sP[r0*PA + kb + 4]);
            uint32_t a3 = __float_as_uint(sP[r1*PA + kb + 4]);
            #pragma unroll
            for (int nt = 0; nt < 4; nt++) {
                int n = wc*32 + nt*8 + g;
                uint32_t b0 = __float_as_uint(sW[kb*PB + n]);
                uint32_t b1 = __float_as_uint(sW[(kb+4)*PB + n]);
                mma8(o[nt], a0, a1, a2, a3, b0, b1);
            }
        }
        float ri0 = 1.f / (rsum[r0][0] + rsum[r0][1]);
        float ri1 = 1.f / (rsum[r1][0] + rsum[r1][1]);
        #pragma unroll
        for (int nt = 0; nt < 4; nt++) {
            int cb = wc*32 + nt*8 + t4*2;
            *(float2*)&out[((size_t)bh*SEQ + s0 + r0)*HD + cb] =
                make_float2(o[nt][0]*ri0, o[nt][1]*ri0);
            *(float2*)&out[((size_t)bh*SEQ + s0 + r1)*HD + cb] =
                make_float2(o[nt][2]*ri1, o[nt][3]*ri1);
        }
        __syncthreads();
    }
}

// ================= launch =================
extern "C" void kernel_launch(void* const* d_in, const int* in_sizes, int n_in,
                              void* d_out, int out_size) {
    const float* Q    = (const float*)d_in[0];
    const float* K    = (const float*)d_in[1];
    const float* V    = (const float*)d_in[2];
    const float* mask = (const float*)d_in[3];
    float* out = (float*)d_out;

    const int SMEM_MID = 5 * NL * PB * sizeof(float);                 // 92160 (inv layout)
    const int SMEM_FIN = (3 * NL * PA + NL * PB) * sizeof(float);     // 70656
    cudaFuncSetAttribute(k_mid,   cudaFuncAttributeMaxDynamicSharedMemorySize, SMEM_MID);
    cudaFuncSetAttribute(k_final, cudaFuncAttributeMaxDynamicSharedMemorySize, SMEM_FIN);

    k_landmarks<<<dim3(NL, BH), HD>>>(Q, K, mask);
    k_kernel2<<<BH, NL>>>();
    k_mid<<<dim3(NSPLIT + 1, BH), 256, SMEM_MID>>>(K, V, mask);
    k_mergewmat<<<BH, 256>>>();
    k_final<<<dim3(SEQ/TS/NTF, BH), 256, SMEM_FIN>>>(Q, mask, out);
}

// round 5
// speedup vs baseline: 1.8029x; 1.2224x over previous
#include <cuda_runtime.h>
#include <math.h>
#include <stdint.h>

#define BATCHN 8
#define NHEAD 12
#define BH 96            // BATCHN*NHEAD
#define SEQ 4096
#define HD 64
#define NL 64            // landmarks
#define SEG 64           // SEQ / NL
#define NSPLIT 8
#define SPLEN 512        // SEQ / NSPLIT
#define TS 64
#define NTF 4            // seq tiles per k_final block
#define SCALE 0.35355339059327373f   // 64^(-1/4)
#define NEGBIG 1000000000.0f
#define PA 68            // pitch for n-row-indexed mma buffers (== 4 mod 32, 16B-aligned rows)
#define PB 72            // pitch for k-row-indexed mma buffers (== 8 mod 32, 16B-aligned rows)
#define PI 65            // pitch for SIMT 64x64 matmuls (scalar access only!)
#define PT 68            // pitch for float4-written SIMT buffer (16B-aligned rows)
#define P2 65

// -------- scratch --------
__device__ float g_Ql[BH*NL*HD];
__device__ float g_Kl[BH*NL*HD];
__device__ float g_K2[BH*NL*NL];
__device__ float g_colmax[BH];
__device__ float g_Inv[BH*NL*NL];
__device__ float g_pacc[BH*NSPLIT*NL*HD];
__device__ float g_pd[BH*NSPLIT*NL];
__device__ float g_W[BH*NL*HD];

__device__ __forceinline__ float tf32r(float x){
    uint32_t u; asm("cvt.rna.tf32.f32 %0, %1;" : "=r"(u) : "f"(x));
    return __uint_as_float(u);
}
__device__ __forceinline__ void mma8(float c[4],
                                     uint32_t a0,uint32_t a1,uint32_t a2,uint32_t a3,
                                     uint32_t b0,uint32_t b1){
    asm volatile("mma.sync.aligned.m16n8k8.row.col.f32.tf32.tf32.f32 "
        "{%0,%1,%2,%3}, {%4,%5,%6,%7}, {%8,%9}, {%0,%1,%2,%3};"
        : "+f"(c[0]),"+f"(c[1]),"+f"(c[2]),"+f"(c[3])
        : "r"(a0),"r"(a1),"r"(a2),"r"(a3),"r"(b0),"r"(b1));
}

// ================= K1: landmarks (256 threads, 4-row load parallelism) =========
__global__ void __launch_bounds__(256) k_landmarks(const float* __restrict__ Q,
                                                   const float* __restrict__ K,
                                                   const float* __restrict__ mask) {
    int bh = blockIdx.y;
    int l  = blockIdx.x;
    int b  = bh / NHEAD;
    int t  = threadIdx.x;
    int c  = t & 63, rg = t >> 6;        // 4 row groups
    __shared__ float redQ[4][NL];
    __shared__ float redK[4][NL];
    const float* qb = Q + ((size_t)bh*SEQ + l*SEG)*HD;
    const float* kb = K + ((size_t)bh*SEQ + l*SEG)*HD;
    const float* mr = mask + (size_t)b*SEQ + l*SEG;
    float sq = 0.f, sk = 0.f;
    #pragma unroll
    for (int k = 0; k < 16; k++) {
        int r = k*4 + rg;
        float m = mr[r];
        sq += qb[r*HD + c] * m;
        sk += kb[r*HD + c] * m;
    }
    redQ[rg][c] = sq;
    redK[rg][c] = sk;
    __syncthreads();
    if (t < NL) {
        float cc = SCALE / (float)SEG;
        float q4 = redQ[0][t] + redQ[1][t] + redQ[2][t] + redQ[3][t];
        float k4 = redK[0][t] + redK[1][t] + redK[2][t] + redK[3][t];
        g_Ql[(bh*NL + l)*HD + t] = q4 * cc;
        g_Kl[(bh*NL + l)*HD + t] = k4 * cc;
    }
}

// ================= K2a: kernel_2 softmax + colsum max =================
__global__ void k_kernel2(void) {
    int bh = blockIdx.x;
    int t  = threadIdx.x;   // 64 threads
    __shared__ float sQ[NL*P2];
    __shared__ float sK[NL*P2];
    __shared__ float sP[NL*P2];
    __shared__ float red[NL];
    for (int r = 0; r < NL; r++) {
        sQ[r*P2 + t] = g_Ql[(bh*NL + r)*HD + t];
        sK[r*P2 + t] = g_Kl[(bh*NL + r)*HD + t];
    }
    __syncthreads();
    int l = t;
    float mx = -1e30f;
    for (int m = 0; m < NL; m++) {
        float s = 0.f;
        #pragma unroll 8
        for (int k = 0; k < HD; k++) s += sQ[l*P2 + k] * sK[m*P2 + k];
        sP[l*P2 + m] = s;
        mx = fmaxf(mx, s);
    }
    float sum = 0.f;
    for (int m = 0; m < NL; m++) {
        float e = __expf(sP[l*P2 + m] - mx);
        sP[l*P2 + m] = e;
        sum += e;
    }
    float inv = 1.f / sum;
    for (int m = 0; m < NL; m++) {
        float v = sP[l*P2 + m] * inv;
        sP[l*P2 + m] = v;
        g_K2[(bh*NL + l)*NL + m] = v;
    }
    __syncthreads();
    float cs = 0.f;
    for (int r = 0; r < NL; r++) cs += sP[r*P2 + t];
    red[t] = cs;
    __syncthreads();
    for (int s = 32; s > 0; s >>= 1) {
        if (t < s) red[t] = fmaxf(red[t], red[t + s]);
        __syncthreads();
    }
    if (t == 0) g_colmax[bh] = red[0];
}

// ===== 64x64 SIMT matmul: C = alpha * A @ (beta*I + gamma*B); C may alias A or B =====
template<int P>
__device__ __forceinline__ void mm64(float* C, const float* A, const float* B,
                                     float beta, float gamma, float alpha, int tid) {
    int i0 = (tid >> 4) << 2;
    int j0 = (tid & 15) << 2;
    float acc[4][4];
    #pragma unroll
    for (int u = 0; u < 4; u++)
        #pragma unroll
        for (int v = 0; v < 4; v++) acc[u][v] = 0.f;
    for (int k = 0; k < HD; k++) {
        float a[4], b[4];
        #pragma unroll
        for (int u = 0; u < 4; u++) a[u] = A[(i0+u)*P + k];
        #pragma unroll
        for (int v = 0; v < 4; v++) {
            float x = B[k*P + j0 + v];
            b[v] = gamma * x + ((k == j0 + v) ? beta : 0.f);
        }
        #pragma unroll
        for (int u = 0; u < 4; u++)
            #pragma unroll
            for (int v = 0; v < 4; v++) acc[u][v] += a[u] * b[v];
    }
    __syncthreads();   // all reads done before any write -> aliasing safe
    #pragma unroll
    for (int u = 0; u < 4; u++)
        #pragma unroll
        for (int v = 0; v < 4; v++) C[(i0+u)*P + j0 + v] = alpha * acc[u][v];
    __syncthreads();
}

// ================= Newton-Schulz pinv body (fp32 SIMT, 4 buffers) =================
__device__ void inv_body(float* sm) {
    float* Km = sm;
    float* Vb = sm + 1*NL*PI;
    float* Pb = sm + 2*NL*PI;
    float* T1 = sm + 3*NL*PI;
    int bh = blockIdx.y;
    int tid = threadIdx.x;
    for (int e = tid; e < NL*NL; e += 256) {
        int r = e >> 6, c = e & 63;
        Km[r*PI + c] = g_K2[bh*NL*NL + e];
    }
    float gmax = -1e30f;
    for (int i = 0; i < BH; i++) gmax = fmaxf(gmax, g_colmax[i]);
    float ig = 1.f / gmax;
    __syncthreads();
    for (int e = tid; e < NL*NL; e += 256) {
        int r = e >> 6, c = e & 63;
        Vb[r*PI + c] = Km[c*PI + r] * ig;
    }
    __syncthreads();
    float *Vp = Vb, *Tp = T1;
    for (int it = 0; it < 6; it++) {
        mm64<PI>(Pb, Km, Vp, 0.f,  1.f, 1.f,   tid);   // P = Km @ V
        mm64<PI>(Tp, Pb, Pb, 7.f, -1.f, 1.f,   tid);   // T = P @ (7I - P)
        mm64<PI>(Pb, Pb, Tp, 15.f,-1.f, 1.f,   tid);   // P = P @ (15I - T)  (C aliases A)
        mm64<PI>(Tp, Vp, Pb, 13.f,-1.f, 0.25f, tid);   // T = 0.25 V @ (13I - P)
        float* t = Vp; Vp = Tp; Tp = t;
    }
    for (int e = tid; e < NL*NL; e += 256) {
        int r = e >> 6, c = e & 63;
        g_Inv[bh*NL*NL + e] = Vp[r*PI + c];
    }
}

// ================= flash kernel_3 @ V body (tf32 mma, no rescale) =================
__device__ void flash3_body(const float* __restrict__ K, const float* __restrict__ V,
                            const float* __restrict__ mask, float* sm) {
    float* sQ = sm;                    // 64 x PA
    float* sK = sm + NL*PA;            // 64 x PA
    float* sV = sm + 2*NL*PA;          // 64 x PB
    float* sP = sm + 2*NL*PA + NL*PB;  // 64 x PA
    __shared__ float sbias[TS];
    __shared__ float dred[NL][2];

    int bh = blockIdx.y, sp = blockIdx.x, b = bh / NHEAD;
    int tid = threadIdx.x, lane = tid & 31, warp = tid >> 5;
    int wr = warp & 3, wc = warp >> 2;
    int g = lane >> 2, t4 = lane & 3;
    int r0 = wr*16 + g, r1 = r0 + 8;

    for (int e4 = tid; e4 < NL*HD/4; e4 += 256) {
        int r = e4 >> 4, c = (e4 & 15) << 2;
        float4 q = *(const float4*)&g_Ql[(size_t)bh*NL*HD + r*HD + c];
        float4 o = make_float4(tf32r(q.x), tf32r(q.y), tf32r(q.z), tf32r(q.w));
        *(float4*)&sQ[r*PA + c] = o;
    }
    float o[4][4];
    #pragma unroll
    for (int nt = 0; nt < 4; nt++)
        #pragma unroll
        for (int j = 0; j < 4; j++) o[nt][j] = 0.f;
    float dp0 = 0.f, dp1 = 0.f;

    for (int tt = 0; tt < SPLEN/TS; tt++) {
        int s0 = sp*SPLEN + tt*TS;
        for (int e4 = tid; e4 < TS*HD/4; e4 += 256) {
            int r = e4 >> 4, c = (e4 & 15) << 2;
            int s = s0 + r;
            float mk = mask[(size_t)b*SEQ + s] * SCALE;
            float4 kk = *(const float4*)&K[((size_t)bh*SEQ + s)*HD + c];
            float4 vv = *(const float4*)&V[((size_t)bh*SEQ + s)*HD + c];
            *(float4*)&sK[r*PA + c] = make_float4(tf32r(kk.x*mk), tf32r(kk.y*mk),
                                                  tf32r(kk.z*mk), tf32r(kk.w*mk));
            *(float4*)&sV[r*PB + c] = make_float4(tf32r(vv.x), tf32r(vv.y),
                                                  tf32r(vv.z), tf32r(vv.w));
        }
        if (tid < TS) sbias[tid] = -NEGBIG * (1.f - mask[(size_t)b*SEQ + s0 + tid]);
        __syncthreads();

        // S = Ql @ Ks^T
        float cf[4][4];
        #pragma unroll
        for (int nt = 0; nt < 4; nt++)
            #pragma unroll
            for (int j = 0; j < 4; j++) cf[nt][j] = 0.f;
        #pragma unroll
        for (int ks = 0; ks < 8; ks++) {
            int kb = ks*8 + t4;
            uint32_t a0 = __float_as_uint(sQ[r0*PA + kb]);
            uint32_t a1 = __float_as_uint(sQ[r1*PA + kb]);
            uint32_t a2 = __float_as_uint(sQ[r0*PA + kb + 4]);
            uint32_t a3 = __float_as_uint(sQ[r1*PA + kb + 4]);
            #pragma unroll
            for (int nt = 0; nt < 4; nt++) {
                int n = wc*32 + nt*8 + g;
                uint32_t b0 = __float_as_uint(sK[n*PA + kb]);
                uint32_t b1 = __float_as_uint(sK[n*PA + kb + 4]);
                mma8(cf[nt], a0, a1, a2, a3, b0, b1);
            }
        }
        #pragma unroll
        for (int nt = 0; nt < 4; nt++) {
            int cb = wc*32 + nt*8 + t4*2;
            float bb0 = sbias[cb], bb1 = sbias[cb+1];
            float e0 = __expf(cf[nt][0] + bb0), e1 = __expf(cf[nt][1] + bb1);
            float e2 = __expf(cf[nt][2] + bb0), e3 = __expf(cf[nt][3] + bb1);
            dp0 += e0 + e1; dp1 += e2 + e3;
            *(float2*)&sP[r0*PA + cb] = make_float2(tf32r(e0), tf32r(e1));
            *(float2*)&sP[r1*PA + cb] = make_float2(tf32r(e2), tf32r(e3));
        }
        __syncthreads();
        // O += P @ V
        #pragma unroll
        for (int ks = 0; ks < 8; ks++) {
            int kb = ks*8 + t4;
            uint32_t a0 = __float_as_uint(sP[r0*PA + kb]);
            uint32_t a1 = __float_as_uint(sP[r1*PA + kb]);
            uint32_t a2 = __float_as_uint(sP[r0*PA + kb + 4]);
            uint32_t a3 = __float_as_uint(sP[r1*PA + kb + 4]);
            #pragma unroll
            for (int nt = 0; nt < 4; nt++) {
                int n = wc*32 + nt*8 + g;
                uint32_t b0 = __float_as_uint(sV[kb*PB + n]);
                uint32_t b1 = __float_as_uint(sV[(kb+4)*PB + n]);
                mma8(o[nt], a0, a1, a2, a3, b0, b1);
            }
        }
        __syncthreads();
    }
    size_t base = ((size_t)bh*NSPLIT + sp)*NL;
    #pragma unroll
    for (int nt = 0; nt < 4; nt++) {
        int cb = wc*32 + nt*8 + t4*2;
        *(float2*)&g_pacc[(base + r0)*HD + cb] = make_float2(o[nt][0], o[nt][1]);
        *(float2*)&g_pacc[(base + r1)*HD + cb] = make_float2(o[nt][2], o[nt][3]);
    }
    dp0 += __shfl_xor_sync(0xffffffffu, dp0, 1);
    dp0 += __shfl_xor_sync(0xffffffffu, dp0, 2);
    dp1 += __shfl_xor_sync(0xffffffffu, dp1, 1);
    dp1 += __shfl_xor_sync(0xffffffffu, dp1, 2);
    if (t4 == 0) { dred[r0][wc] = dp0; dred[r1][wc] = dp1; }
    __syncthreads();
    if (tid < NL) g_pd[base + tid] = dred[tid][0] + dred[tid][1];
}

// ================= fused middle kernel: flash3 (x<8) || inv (x==8) =================
__global__ void __launch_bounds__(256, 3) k_mid(const float* __restrict__ K,
                                                const float* __restrict__ V,
                                                const float* __restrict__ mask) {
    extern __shared__ float sm[];
    if (blockIdx.x < NSPLIT) flash3_body(K, V, mask, sm);
    else                     inv_body(sm);
}

// ================= merge partials + W = Inv @ T3V =================
__global__ void __launch_bounds__(256) k_mergewmat(void) {
    __shared__ float A[NL*PI];
    __shared__ float T[NL*PT];
    __shared__ float dtot[NL];
    int bh = blockIdx.x, tid = threadIdx.x;
    for (int e = tid; e < NL*NL; e += 256) {
        int r = e >> 6, c = e & 63;
        A[r*PI + c] = g_Inv[bh*NL*NL + e];
    }
    if (tid < NL) {
        float s = 0.f;
        #pragma unroll
        for (int k = 0; k < NSPLIT; k++) s += g_pd[((size_t)bh*NSPLIT + k)*NL + tid];
        dtot[tid] = s;
    }
    __syncthreads();
    for (int e4 = tid; e4 < NL*HD/4; e4 += 256) {
        int r = e4 >> 4, c = (e4 & 15) << 2;
        float4 acc = make_float4(0.f, 0.f, 0.f, 0.f);
        #pragma unroll
        for (int s = 0; s < NSPLIT; s++) {
            float4 p = *(const float4*)&g_pacc[(((size_t)bh*NSPLIT + s)*NL + r)*HD + c];
            acc.x += p.x; acc.y += p.y; acc.z += p.z; acc.w += p.w;
        }
        float id = 1.f / dtot[r];
        *(float4*)&T[r*PT + c] = make_float4(acc.x*id, acc.y*id, acc.z*id, acc.w*id);
    }
    __syncthreads();
    int i0 = (tid >> 4) << 2;
    int j0 = (tid & 15) << 2;
    float acc[4][4];
    #pragma unroll
    for (int u = 0; u < 4; u++)
        #pragma unroll
        for (int v = 0; v < 4; v++) acc[u][v] = 0.f;
    for (int k = 0; k < NL; k++) {
        float a[4], b[4];
        #pragma unroll
        for (int u = 0; u < 4; u++) a[u] = A[(i0+u)*PI + k];
        #pragma unroll
        for (int v = 0; v < 4; v++) b[v] = T[k*PT + j0 + v];
        #pragma unroll
        for (int u = 0; u < 4; u++)
            #pragma unroll
            for (int v = 0; v < 4; v++) acc[u][v] += a[u] * b[v];
    }
    #pragma unroll
    for (int u = 0; u < 4; u++)
        #pragma unroll
        for (int v = 0; v < 4; v++)
            g_W[((size_t)bh*NL + i0 + u)*HD + j0 + v] = acc[u][v];
}

// ================= K5: X = softmax(Qs K_l^T) @ W  (tf32 mma) =================
__global__ void __launch_bounds__(256, 3) k_final(const float* __restrict__ Q,
                                                  const float* __restrict__ mask,
                                                  float* __restrict__ out) {
    extern __shared__ float sm[];
    float* sKl = sm;                   // 64 x PA
    float* sQ  = sm + NL*PA;           // 64 x PA
    float* sP  = sm + 2*NL*PA;         // 64 x PA
    float* sW  = sm + 3*NL*PA;         // 64 x PB
    __shared__ float rsum[NL][2];

    int bh = blockIdx.y, b = bh / NHEAD;
    int tid = threadIdx.x, lane = tid & 31, warp = tid >> 5;
    int wr = warp & 3, wc = warp >> 2;
    int g = lane >> 2, t4 = lane & 3;
    int r0 = wr*16 + g, r1 = r0 + 8;

    for (int e4 = tid; e4 < NL*HD/4; e4 += 256) {
        int r = e4 >> 4, c = (e4 & 15) << 2;
        float4 kl = *(const float4*)&g_Kl[(size_t)bh*NL*HD + r*HD + c];
        float4 w  = *(const float4*)&g_W[(size_t)bh*NL*HD + r*HD + c];
        *(float4*)&sKl[r*PA + c] = make_float4(tf32r(kl.x), tf32r(kl.y), tf32r(kl.z), tf32r(kl.w));
        *(float4*)&sW[r*PB + c]  = make_float4(tf32r(w.x), tf32r(w.y), tf32r(w.z), tf32r(w.w));
    }
    for (int tt = 0; tt < NTF; tt++) {
        int s0 = (blockIdx.x*NTF + tt)*TS;
        for (int e4 = tid; e4 < TS*HD/4; e4 += 256) {
            int r = e4 >> 4, c = (e4 & 15) << 2;
            int s = s0 + r;
            float mk = mask[(size_t)b*SEQ + s] * SCALE;
            float4 q = *(const float4*)&Q[((size_t)bh*SEQ + s)*HD + c];
            *(float4*)&sQ[r*PA + c] = make_float4(tf32r(q.x*mk), tf32r(q.y*mk),
                                                  tf32r(q.z*mk), tf32r(q.w*mk));
        }
        __syncthreads();
        float cf[4][4];
        #pragma unroll
        for (int nt = 0; nt < 4; nt++)
            #pragma unroll
            for (int j = 0; j < 4; j++) cf[nt][j] = 0.f;
        #pragma unroll
        for (int ks = 0; ks < 8; ks++) {
            int kb = ks*8 + t4;
            uint32_t a0 = __float_as_uint(sQ[r0*PA + kb]);
            uint32_t a1 = __float_as_uint(sQ[r1*PA + kb]);
            uint32_t a2 = __float_as_uint(sQ[r0*PA + kb + 4]);
            uint32_t a3 = __float_as_uint(sQ[r1*PA + kb + 4]);
            #pragma unroll
            for (int nt = 0; nt < 4; nt++) {
                int n = wc*32 + nt*8 + g;
                uint32_t b0 = __float_as_uint(sKl[n*PA + kb]);
                uint32_t b1 = __float_as_uint(sKl[n*PA + kb + 4]);
                mma8(cf[nt], a0, a1, a2, a3, b0, b1);
            }
        }
        float dp0 = 0.f, dp1 = 0.f;
        #pragma unroll
        for (int nt = 0; nt < 4; nt++) {
            int cb = wc*32 + nt*8 + t4*2;
            float e0 = __expf(cf[nt][0]), e1 = __expf(cf[nt][1]);
            float e2 = __expf(cf[nt][2]), e3 = __expf(cf[nt][3]);
            dp0 += e0 + e1; dp1 += e2 + e3;
            *(float2*)&sP[r0*PA + cb] = make_float2(tf32r(e0), tf32r(e1));
            *(float2*)&sP[r1*PA + cb] = make_float2(tf32r(e2), tf32r(e3));
        }
        dp0 += __shfl_xor_sync(0xffffffffu, dp0, 1);
        dp0 += __shfl_xor_sync(0xffffffffu, dp0, 2);
        dp1 += __shfl_xor_sync(0xffffffffu, dp1, 1);
        dp1 += __shfl_xor_sync(0xffffffffu, dp1, 2);
        if (t4 == 0) { rsum[r0][wc] = dp0; rsum[r1][wc] = dp1; }
        __syncthreads();
        float o[4][4];
        #pragma unroll
        for (int nt = 0; nt < 4; nt++)
            #pragma unroll
            for (int j = 0; j < 4; j++) o[nt][j] = 0.f;
        #pragma unroll
        for (int ks = 0; ks < 8; ks++) {
            int kb = ks*8 + t4;
            uint32_t a0 = __float_as_uint(sP[r0*PA + kb]);
            uint32_t a1 = __float_as_uint(sP[r1*PA + kb]);
            uint32_t a2 = __float_as_uint(sP[r0*PA + kb + 4]);
            uint32_t a3 = __float_as_uint(sP[r1*PA + kb + 4]);
            #pragma unroll
            for (int nt = 0; nt < 4; nt++) {
                int n = wc*32 + nt*8 + g;
                uint32_t b0 = __float_as_uint(sW[kb*PB + n]);
                uint32_t b1 = __float_as_uint(sW[(kb+4)*PB + n]);
                mma8(o[nt], a0, a1, a2, a3, b0, b1);
            }
        }
        float ri0 = 1.f / (rsum[r0][0] + rsum[r0][1]);
        float ri1 = 1.f / (rsum[r1][0] + rsum[r1][1]);
        #pragma unroll
        for (int nt = 0; nt < 4; nt++) {
            int cb = wc*32 + nt*8 + t4*2;
            *(float2*)&out[((size_t)bh*SEQ + s0 + r0)*HD + cb] =
                make_float2(o[nt][0]*ri0, o[nt][1]*ri0);
            *(float2*)&out[((size_t)bh*SEQ + s0 + r1)*HD + cb] =
                make_float2(o[nt][2]*ri1, o[nt][3]*ri1);
        }
        __syncthreads();
    }
}

// ================= launch =================
extern "C" void kernel_launch(void* const* d_in, const int* in_sizes, int n_in,
                              void* d_out, int out_size) {
    const float* Q    = (const float*)d_in[0];
    const float* K    = (const float*)d_in[1];
    const float* V    = (const float*)d_in[2];
    const float* mask = (const float*)d_in[3];
    float* out = (float*)d_out;

    const int SMEM_MID = (3 * NL * PA + NL * PB) * sizeof(float);     // 70656
    const int SMEM_FIN = (3 * NL * PA + NL * PB) * sizeof(float);     // 70656
    cudaFuncSetAttribute(k_mid,   cudaFuncAttributeMaxDynamicSharedMemorySize, SMEM_MID);
    cudaFuncSetAttribute(k_final, cudaFuncAttributeMaxDynamicSharedMemorySize, SMEM_FIN);

    k_landmarks<<<dim3(NL, BH), 256>>>(Q, K, mask);
    k_kernel2<<<BH, NL>>>();
    k_mid<<<dim3(NSPLIT + 1, BH), 256, SMEM_MID>>>(K, V, mask);
    k_mergewmat<<<BH, 256>>>();
    k_final<<<dim3(SEQ/TS/NTF, BH), 256, SMEM_FIN>>>(Q, mask, out);
}

// round 9
// speedup vs baseline: 1.8930x; 1.0500x over previous
#include <cuda_runtime.h>
#include <math.h>
#include <stdint.h>

#define BATCHN 8
#define NHEAD 12
#define BH 96            // BATCHN*NHEAD
#define SEQ 4096
#define HD 64
#define NL 64            // landmarks
#define SEG 64           // SEQ / NL
#define NSPLIT 8
#define SPLEN 512        // SEQ / NSPLIT
#define TS 64
#define NTF 4            // seq tiles per k_final block
#define SCALE 0.35355339059327373f   // 64^(-1/4)
#define NEGBIG 1000000000.0f
#define PA 68            // pitch for n-row-indexed mma buffers (== 4 mod 32, 16B rows)
#define PB 72            // pitch for k-row-indexed mma buffers (== 8 mod 32, 16B rows)
#define PI 65            // pitch for SIMT 64x64 matmuls (scalar access only!)
#define PT 68
#define P2 65

// -------- scratch --------
__device__ float g_Ql[BH*NL*HD];
__device__ float g_Kl[BH*NL*HD];
__device__ float g_K2[BH*NL*NL];
__device__ float g_colmax[BH];
__device__ float g_Inv[BH*NL*NL];
__device__ float g_pacc[BH*NSPLIT*NL*HD];
__device__ float g_pd[BH*NSPLIT*NL];
__device__ float g_W[BH*NL*HD];

__device__ __forceinline__ float tf32r(float x){
    uint32_t u; asm("cvt.rna.tf32.f32 %0, %1;" : "=r"(u) : "f"(x));
    return __uint_as_float(u);
}
// load + round-to-nearest tf32 (for raw cp.async-staged smem operands)
__device__ __forceinline__ uint32_t tf32u(float x){
    uint32_t u; asm("cvt.rna.tf32.f32 %0, %1;" : "=r"(u) : "f"(x));
    return u;
}
__device__ __forceinline__ void mma8(float c[4],
                                     uint32_t a0,uint32_t a1,uint32_t a2,uint32_t a3,
                                     uint32_t b0,uint32_t b1){
    asm volatile("mma.sync.aligned.m16n8k8.row.col.f32.tf32.tf32.f32 "
        "{%0,%1,%2,%3}, {%4,%5,%6,%7}, {%8,%9}, {%0,%1,%2,%3};"
        : "+f"(c[0]),"+f"(c[1]),"+f"(c[2]),"+f"(c[3])
        : "r"(a0),"r"(a1),"r"(a2),"r"(a3),"r"(b0),"r"(b1));
}
__device__ __forceinline__ uint32_t smem_u32(const void* p){
    return (uint32_t)__cvta_generic_to_shared(p);
}
__device__ __forceinline__ void cpa16(uint32_t d, const void* s){
    asm volatile("cp.async.cg.shared.global [%0], [%1], 16;" :: "r"(d), "l"(s));
}
__device__ __forceinline__ void cp_commit(){ asm volatile("cp.async.commit_group;"); }
template<int N> __device__ __forceinline__ void cp_wait(){
    asm volatile("cp.async.wait_group %0;" :: "n"(N));
}

// ================= K1: landmarks (float4, 16-deep MLP) =================
__global__ void __launch_bounds__(256) k_landmarks(const float* __restrict__ Q,
                                                   const float* __restrict__ K,
                                                   const float* __restrict__ mask) {
    int bh = blockIdx.y;
    int l  = blockIdx.x;
    int b  = bh / NHEAD;
    int t  = threadIdx.x;
    int c4 = (t & 15) << 2;
    int rg = t >> 4;                 // 16 row groups of 4 rows
    __shared__ float redQ[16][68];
    __shared__ float redK[16][68];
    const float* qb = Q + ((size_t)bh*SEQ + l*SEG)*HD;
    const float* kb = K + ((size_t)bh*SEQ + l*SEG)*HD;
    const float* mr = mask + (size_t)b*SEQ + l*SEG;
    float sq0=0.f,sq1=0.f,sq2=0.f,sq3=0.f;
    float sk0=0.f,sk1=0.f,sk2=0.f,sk3=0.f;
    #pragma unroll
    for (int k = 0; k < 4; k++) {
        int r = rg + k*16;
        float m = mr[r];
        float4 q = *(const float4*)(qb + r*HD + c4);
        float4 kk = *(const float4*)(kb + r*HD + c4);
        sq0 += q.x*m; sq1 += q.y*m; sq2 += q.z*m; sq3 += q.w*m;
        sk0 += kk.x*m; sk1 += kk.y*m; sk2 += kk.z*m; sk3 += kk.w*m;
    }
    *(float4*)&redQ[rg][c4] = make_float4(sq0,sq1,sq2,sq3);
    *(float4*)&redK[rg][c4] = make_float4(sk0,sk1,sk2,sk3);
    __syncthreads();
    if (t < NL) {
        float aq = 0.f, ak = 0.f;
        #pragma unroll
        for (int g = 0; g < 16; g++) { aq += redQ[g][t]; ak += redK[g][t]; }
        float cc = SCALE / (float)SEG;
        g_Ql[(bh*NL + l)*HD + t] = aq * cc;
        g_Kl[(bh*NL + l)*HD + t] = ak * cc;
    }
}

// ================= K2a: kernel_2 softmax + colsum max =================
__global__ void k_kernel2(void) {
    int bh = blockIdx.x;
    int t  = threadIdx.x;   // 64 threads
    __shared__ float sQ[NL*P2];
    __shared__ float sK[NL*P2];
    __shared__ float sP[NL*P2];
    __shared__ float red[NL];
    for (int r = 0; r < NL; r++) {
        sQ[r*P2 + t] = g_Ql[(bh*NL + r)*HD + t];
        sK[r*P2 + t] = g_Kl[(bh*NL + r)*HD + t];
    }
    __syncthreads();
    int l = t;
    float mx = -1e30f;
    for (int m = 0; m < NL; m++) {
        float s = 0.f;
        #pragma unroll 8
        for (int k = 0; k < HD; k++) s += sQ[l*P2 + k] * sK[m*P2 + k];
        sP[l*P2 + m] = s;
        mx = fmaxf(mx, s);
    }
    float sum = 0.f;
    for (int m = 0; m < NL; m++) {
        float e = __expf(sP[l*P2 + m] - mx);
        sP[l*P2 + m] = e;
        sum += e;
    }
    float inv = 1.f / sum;
    for (int m = 0; m < NL; m++) {
        float v = sP[l*P2 + m] * inv;
        sP[l*P2 + m] = v;
        g_K2[(bh*NL + l)*NL + m] = v;
    }
    __syncthreads();
    float cs = 0.f;
    for (int r = 0; r < NL; r++) cs += sP[r*P2 + t];
    red[t] = cs;
    __syncthreads();
    for (int s = 32; s > 0; s >>= 1) {
        if (t < s) red[t] = fmaxf(red[t], red[t + s]);
        __syncthreads();
    }
    if (t == 0) g_colmax[bh] = red[0];
}

// ===== 64x64 SIMT matmul: C = alpha * A @ (beta*I + gamma*B); C may alias A or B =====
template<int P>
__device__ __forceinline__ void mm64(float* C, const float* A, const float* B,
                                     float beta, float gamma, float alpha, int tid) {
    int i0 = (tid >> 4) << 2;
    int j0 = (tid & 15) << 2;
    float acc[4][4];
    #pragma unroll
    for (int u = 0; u < 4; u++)
        #pragma unroll
        for (int v = 0; v < 4; v++) acc[u][v] = 0.f;
    for (int k = 0; k < HD; k++) {
        float a[4], b[4];
        #pragma unroll
        for (int u = 0; u < 4; u++) a[u] = A[(i0+u)*P + k];
        #pragma unroll
        for (int v = 0; v < 4; v++) {
            float x = B[k*P + j0 + v];
            b[v] = gamma * x + ((k == j0 + v) ? beta : 0.f);
        }
        #pragma unroll
        for (int u = 0; u < 4; u++)
            #pragma unroll
            for (int v = 0; v < 4; v++) acc[u][v] += a[u] * b[v];
    }
    __syncthreads();
    #pragma unroll
    for (int u = 0; u < 4; u++)
        #pragma unroll
        for (int v = 0; v < 4; v++) C[(i0+u)*P + j0 + v] = alpha * acc[u][v];
    __syncthreads();
}

// ================= Newton-Schulz pinv body (fp32 SIMT, 4 buffers) =================
__device__ void inv_body(float* sm) {
    float* Km = sm;
    float* Vb = sm + 1*NL*PI;
    float* Pb = sm + 2*NL*PI;
    float* T1 = sm + 3*NL*PI;
    int bh = blockIdx.y;
    int tid = threadIdx.x;
    for (int e = tid; e < NL*NL; e += 256) {
        int r = e >> 6, c = e & 63;
        Km[r*PI + c] = g_K2[bh*NL*NL + e];
    }
    float gmax = -1e30f;
    for (int i = 0; i < BH; i++) gmax = fmaxf(gmax, g_colmax[i]);
    float ig = 1.f / gmax;
    __syncthreads();
    for (int e = tid; e < NL*NL; e += 256) {
        int r = e >> 6, c = e & 63;
        Vb[r*PI + c] = Km[c*PI + r] * ig;
    }
    __syncthreads();
    float *Vp = Vb, *Tp = T1;
    for (int it = 0; it < 6; it++) {
        mm64<PI>(Pb, Km, Vp, 0.f,  1.f, 1.f,   tid);
        mm64<PI>(Tp, Pb, Pb, 7.f, -1.f, 1.f,   tid);
        mm64<PI>(Pb, Pb, Tp, 15.f,-1.f, 1.f,   tid);
        mm64<PI>(Tp, Vp, Pb, 13.f,-1.f, 0.25f, tid);
        float* t = Vp; Vp = Tp; Tp = t;
    }
    for (int e = tid; e < NL*NL; e += 256) {
        int r = e >> 6, c = e & 63;
        g_Inv[bh*NL*NL + e] = Vp[r*PI + c];
    }
}

// ====== flash3 prefetch: raw K/V tiles + mask tile via cp.async ======
__device__ __forceinline__ void f3_prefetch(const float* K, const float* V,
                                            const float* mask, float* sKb, float* sVb,
                                            float* smaskb, int bh, int b, int s0, int tid){
    const float* Kb = K + ((size_t)bh*SEQ + s0)*HD;
    const float* Vb = V + ((size_t)bh*SEQ + s0)*HD;
    #pragma unroll
    for (int i = 0; i < 4; i++) {
        int e4 = tid + i*256;
        int r = e4 >> 4, c = (e4 & 15) << 2;
        cpa16(smem_u32(&sKb[r*PA + c]), Kb + r*HD + c);
        cpa16(smem_u32(&sVb[r*PB + c]), Vb + r*HD + c);
    }
    if (tid < 16) cpa16(smem_u32(&smaskb[tid*4]), mask + (size_t)b*SEQ + s0 + tid*4);
}

// ================= flash kernel_3 @ V body (tf32 mma, cp.async double buffer) ===========
__device__ void flash3_body(const float* __restrict__ K, const float* __restrict__ V,
                            const float* __restrict__ mask, float* sm) {
    float* sQ  = sm;                      // 64 x PA  (rounded at staging)
    float* sP  = sm + NL*PA;              // 64 x PA  (rounded at staging)
    float* sK0 = sm + 2*NL*PA;            // 64 x PA  (raw; rounded on fragment load)
    float* sK1 = sm + 3*NL*PA;            // 64 x PA
    float* sV0 = sm + 4*NL*PA;            // 64 x PB
    float* sV1 = sm + 4*NL*PA + NL*PB;    // 64 x PB
    __shared__ float smask[2][TS];
    __shared__ float dred[NL][2];

    int bh = blockIdx.y, sp = blockIdx.x, b = bh / NHEAD;
    int tid = threadIdx.x, lane = tid & 31, warp = tid >> 5;
    int wr = warp & 3, wc = warp >> 2;
    int g = lane >> 2, t4 = lane & 3;
    int r0 = wr*16 + g, r1 = r0 + 8;

    // prefetch tiles 0,1
    f3_prefetch(K, V, mask, sK0, sV0, smask[0], bh, b, sp*SPLEN + 0*TS, tid); cp_commit();
    f3_prefetch(K, V, mask, sK1, sV1, smask[1], bh, b, sp*SPLEN + 1*TS, tid); cp_commit();

    // stage sQ = rna(Ql * SCALE)  (carries the SCALE^2 since K is raw)
    for (int e4 = tid; e4 < NL*HD/4; e4 += 256) {
        int r = e4 >> 4, c = (e4 & 15) << 2;
        float4 q = *(const float4*)&g_Ql[(size_t)bh*NL*HD + r*HD + c];
        *(float4*)&sQ[r*PA + c] = make_float4(tf32r(q.x*SCALE), tf32r(q.y*SCALE),
                                              tf32r(q.z*SCALE), tf32r(q.w*SCALE));
    }
    float o[4][4];
    #pragma unroll
    for (int nt = 0; nt < 4; nt++)
        #pragma unroll
        for (int j = 0; j < 4; j++) o[nt][j] = 0.f;
    float dp0 = 0.f, dp1 = 0.f;

    for (int tt = 0; tt < SPLEN/TS; tt++) {
        int buf = tt & 1;
        float* sK = buf ? sK1 : sK0;
        float* sV = buf ? sV1 : sV0;
        cp_wait<1>();
        __syncthreads();

        // S = Ql @ Ks^T  (K fragments rounded in-register)
        float cf[4][4];
        #pragma unroll
        for (int nt = 0; nt < 4; nt++)
            #pragma unroll
            for (int j = 0; j < 4; j++) cf[nt][j] = 0.f;
        #pragma unroll
        for (int ks = 0; ks < 8; ks++) {
            int kb = ks*8 + t4;
            uint32_t a0 = __float_as_uint(sQ[r0*PA + kb]);
            uint32_t a1 = __float_as_uint(sQ[r1*PA + kb]);
            uint32_t a2 = __float_as_uint(sQ[r0*PA + kb + 4]);
            uint32_t a3 = __float_as_uint(sQ[r1*PA + kb + 4]);
            #pragma unroll
            for (int nt = 0; nt < 4; nt++) {
                int n = wc*32 + nt*8 + g;
                uint32_t b0 = tf32u(sK[n*PA + kb]);
                uint32_t b1 = tf32u(sK[n*PA + kb + 4]);
                mma8(cf[nt], a0, a1, a2, a3, b0, b1);
            }
        }
        #pragma unroll
        for (int nt = 0; nt < 4; nt++) {
            int cb = wc*32 + nt*8 + t4*2;
            float bb0 = -NEGBIG * (1.f - smask[buf][cb]);
            float bb1 = -NEGBIG * (1.f - smask[buf][cb+1]);
            float e0 = __expf(cf[nt][0] + bb0), e1 = __expf(cf[nt][1] + bb1);
            float e2 = __expf(cf[nt][2] + bb0), e3 = __expf(cf[nt][3] + bb1);
            dp0 += e0 + e1; dp1 += e2 + e3;
            *(float2*)&sP[r0*PA + cb] = make_float2(tf32r(e0), tf32r(e1));
            *(float2*)&sP[r1*PA + cb] = make_float2(tf32r(e2), tf32r(e3));
        }
        __syncthreads();
        // O += P @ V  (V fragments rounded in-register)
        #pragma unroll
        for (int ks = 0; ks < 8; ks++) {
            int kb = ks*8 + t4;
            uint32_t a0 = __float_as_uint(sP[r0*PA + kb]);
            uint32_t a1 = __float_as_uint(sP[r1*PA + kb]);
            uint32_t a2 = __float_as_uint(sP[r0*PA + kb + 4]);
            uint32_t a3 = __float_as_uint(sP[r1*PA + kb + 4]);
            #pragma unroll
            for (int nt = 0; nt < 4; nt++) {
                int n = wc*32 + nt*8 + g;
                uint32_t b0 = tf32u(sV[kb*PB + n]);
                uint32_t b1 = tf32u(sV[(kb+4)*PB + n]);
                mma8(o[nt], a0, a1, a2, a3, b0, b1);
            }
        }
        __syncthreads();
        if (tt + 2 < SPLEN/TS) {
            f3_prefetch(K, V, mask, sK, sV, smask[buf], bh, b,
                        sp*SPLEN + (tt+2)*TS, tid);
            cp_commit();
        }
    }
    size_t base = ((size_t)bh*NSPLIT + sp)*NL;
    #pragma unroll
    for (int nt = 0; nt < 4; nt++) {
        int cb = wc*32 + nt*8 + t4*2;
        *(float2*)&g_pacc[(base + r0)*HD + cb] = make_float2(o[nt][0], o[nt][1]);
        *(float2*)&g_pacc[(base + r1)*HD + cb] = make_float2(o[nt][2], o[nt][3]);
    }
    dp0 += __shfl_xor_sync(0xffffffffu, dp0, 1);
    dp0 += __shfl_xor_sync(0xffffffffu, dp0, 2);
    dp1 += __shfl_xor_sync(0xffffffffu, dp1, 1);
    dp1 += __shfl_xor_sync(0xffffffffu, dp1, 2);
    if (t4 == 0) { dred[r0][wc] = dp0; dred[r1][wc] = dp1; }
    __syncthreads();
    if (tid < NL) g_pd[base + tid] = dred[tid][0] + dred[tid][1];
}

// ================= fused middle kernel: flash3 (x<8) || inv (x==8) =================
__global__ void __launch_bounds__(256, 2) k_mid(const float* __restrict__ K,
                                                const float* __restrict__ V,
                                                const float* __restrict__ mask) {
    extern __shared__ float sm[];
    if (blockIdx.x < NSPLIT) flash3_body(K, V, mask, sm);
    else                     inv_body(sm);
}

// ================= merge partials + W = Inv @ T3V =================
__global__ void __launch_bounds__(256) k_mergewmat(void) {
    __shared__ float A[NL*PI];
    __shared__ float T[NL*PT];
    __shared__ float dtot[NL];
    int bh = blockIdx.x, tid = threadIdx.x;
    for (int e = tid; e < NL*NL; e += 256) {
        int r = e >> 6, c = e & 63;
        A[r*PI + c] = g_Inv[bh*NL*NL + e];
    }
    if (tid < NL) {
        float s = 0.f;
        #pragma unroll
        for (int k = 0; k < NSPLIT; k++) s += g_pd[((size_t)bh*NSPLIT + k)*NL + tid];
        dtot[tid] = s;
    }
    __syncthreads();
    for (int e4 = tid; e4 < NL*HD/4; e4 += 256) {
        int r = e4 >> 4, c = (e4 & 15) << 2;
        float4 acc = make_float4(0.f, 0.f, 0.f, 0.f);
        #pragma unroll
        for (int s = 0; s < NSPLIT; s++) {
            float4 p = *(const float4*)&g_pacc[(((size_t)bh*NSPLIT + s)*NL + r)*HD + c];
            acc.x += p.x; acc.y += p.y; acc.z += p.z; acc.w += p.w;
        }
        float id = 1.f / dtot[r];
        *(float4*)&T[r*PT + c] = make_float4(acc.x*id, acc.y*id, acc.z*id, acc.w*id);
    }
    __syncthreads();
    int i0 = (tid >> 4) << 2;
    int j0 = (tid & 15) << 2;
    float acc[4][4];
    #pragma unroll
    for (int u = 0; u < 4; u++)
        #pragma unroll
        for (int v = 0; v < 4; v++) acc[u][v] = 0.f;
    for (int k = 0; k < NL; k++) {
        float a[4], b[4];
        #pragma unroll
        for (int u = 0; u < 4; u++) a[u] = A[(i0+u)*PI + k];
        #pragma unroll
        for (int v = 0; v < 4; v++) b[v] = T[k*PT + j0 + v];
        #pragma unroll
        for (int u = 0; u < 4; u++)
            #pragma unroll
            for (int v = 0; v < 4; v++) acc[u][v] += a[u] * b[v];
    }
    #pragma unroll
    for (int u = 0; u < 4; u++)
        #pragma unroll
        for (int v = 0; v < 4; v++)
            g_W[((size_t)bh*NL + i0 + u)*HD + j0 + v] = acc[u][v];
}

// ================= K5: X = softmax(Qs K_l^T) @ W  (cp.async Q tiles) =================
__global__ void __launch_bounds__(256, 2) k_final(const float* __restrict__ Q,
                                                  const float* __restrict__ mask,
                                                  float* __restrict__ out) {
    extern __shared__ float sm[];
    float* sKl = sm;                     // 64 x PA  (rounded at staging)
    float* sP  = sm + NL*PA;             // 64 x PA  (rounded at staging)
    float* sQ0 = sm + 2*NL*PA;           // 64 x PA  (raw; rounded on fragment load)
    float* sQ1 = sm + 3*NL*PA;           // 64 x PA
    float* sW  = sm + 4*NL*PA;           // 64 x PB  (rounded at staging)
    __shared__ float smk[2][TS];
    __shared__ float rsum[NL][2];

    int bh = blockIdx.y, b = bh / NHEAD;
    int tid = threadIdx.x, lane = tid & 31, warp = tid >> 5;
    int wr = warp & 3, wc = warp >> 2;
    int g = lane >> 2, t4 = lane & 3;
    int r0 = wr*16 + g, r1 = r0 + 8;

    // prefetch Q tiles 0,1 (raw) + mask
    #pragma unroll
    for (int p = 0; p < 2; p++) {
        int s0 = (blockIdx.x*NTF + p)*TS;
        const float* Qb = Q + ((size_t)bh*SEQ + s0)*HD;
        float* dst = p ? sQ1 : sQ0;
        #pragma unroll
        for (int i = 0; i < 4; i++) {
            int e4 = tid + i*256;
            int r = e4 >> 4, c = (e4 & 15) << 2;
            cpa16(smem_u32(&dst[r*PA + c]), Qb + r*HD + c);
        }
        if (tid < 16) cpa16(smem_u32(&smk[p][tid*4]), mask + (size_t)b*SEQ + s0 + tid*4);
        cp_commit();
    }

    for (int e4 = tid; e4 < NL*HD/4; e4 += 256) {
        int r = e4 >> 4, c = (e4 & 15) << 2;
        float4 kl = *(const float4*)&g_Kl[(size_t)bh*NL*HD + r*HD + c];
        float4 w  = *(const float4*)&g_W[(size_t)bh*NL*HD + r*HD + c];
        *(float4*)&sKl[r*PA + c] = make_float4(tf32r(kl.x), tf32r(kl.y), tf32r(kl.z), tf32r(kl.w));
        *(float4*)&sW[r*PB + c]  = make_float4(tf32r(w.x), tf32r(w.y), tf32r(w.z), tf32r(w.w));
    }

    for (int tt = 0; tt < NTF; tt++) {
        int buf = tt & 1;
        float* sQ = buf ? sQ1 : sQ0;
        cp_wait<1>();
        __syncthreads();
        // S = Q_raw @ Kl^T (Q fragments rounded in-register); row factor mask*SCALE post-mma
        float cf[4][4];
        #pragma unroll
        for (int nt = 0; nt < 4; nt++)
            #pragma unroll
            for (int j = 0; j < 4; j++) cf[nt][j] = 0.f;
        #pragma unroll
        for (int ks = 0; ks < 8; ks++) {
            int kb = ks*8 + t4;
            uint32_t a0 = tf32u(sQ[r0*PA + kb]);
            uint32_t a1 = tf32u(sQ[r1*PA + kb]);
            uint32_t a2 = tf32u(sQ[r0*PA + kb + 4]);
            uint32_t a3 = tf32u(sQ[r1*PA + kb + 4]);
            #pragma unroll
            for (int nt = 0; nt < 4; nt++) {
                int n = wc*32 + nt*8 + g;
                uint32_t b0 = __float_as_uint(sKl[n*PA + kb]);
                uint32_t b1 = __float_as_uint(sKl[n*PA + kb + 4]);
                mma8(cf[nt], a0, a1, a2, a3, b0, b1);
            }
        }
        float f0 = smk[buf][r0] * SCALE;
        float f1 = smk[buf][r1] * SCALE;
        float dp0 = 0.f, dp1 = 0.f;
        #pragma unroll
        for (int nt = 0; nt < 4; nt++) {
            int cb = wc*32 + nt*8 + t4*2;
            float e0 = __expf(cf[nt][0]*f0), e1 = __expf(cf[nt][1]*f0);
            float e2 = __expf(cf[nt][2]*f1), e3 = __expf(cf[nt][3]*f1);
            dp0 += e0 + e1; dp1 += e2 + e3;
            *(float2*)&sP[r0*PA + cb] = make_float2(tf32r(e0), tf32r(e1));
            *(float2*)&sP[r1*PA + cb] = make_float2(tf32r(e2), tf32r(e3));
        }
        dp0 += __shfl_xor_sync(0xffffffffu, dp0, 1);
        dp0 += __shfl_xor_sync(0xffffffffu, dp0, 2);
        dp1 += __shfl_xor_sync(0xffffffffu, dp1, 1);
        dp1 += __shfl_xor_sync(0xffffffffu, dp1, 2);
        if (t4 == 0) { rsum[r0][wc] = dp0; rsum[r1][wc] = dp1; }
        __syncthreads();
        float o[4][4];
        #pragma unroll
        for (int nt = 0; nt < 4; nt++)
            #pragma unroll
            for (int j = 0; j < 4; j++) o[nt][j] = 0.f;
        #pragma unroll
        for (int ks = 0; ks < 8; ks++) {
            int kb = ks*8 + t4;
            uint32_t a0 = __float_as_uint(sP[r0*PA + kb]);
            uint32_t a1 = __float_as_uint(sP[r1*PA + kb]);
            uint32_t a2 = __float_as_uint(sP[r0*PA + kb + 4]);
            uint32_t a3 = __float_as_uint(sP[r1*PA + kb + 4]);
            #pragma unroll
            for (int nt = 0; nt < 4; nt++) {
                int n = wc*32 + nt*8 + g;
                uint32_t b0 = __float_as_uint(sW[kb*PB + n]);
                uint32_t b1 = __float_as_uint(sW[(kb+4)*PB + n]);
                mma8(o[nt], a0, a1, a2, a3, b0, b1);
            }
        }
        int s0 = (blockIdx.x*NTF + tt)*TS;
        float ri0 = 1.f / (rsum[r0][0] + rsum[r0][1]);
        float ri1 = 1.f / (rsum[r1][0] + rsum[r1][1]);
        #pragma unroll
        for (int nt = 0; nt < 4; nt++) {
            int cb = wc*32 + nt*8 + t4*2;
            *(float2*)&out[((size_t)bh*SEQ + s0 + r0)*HD + cb] =
                make_float2(o[nt][0]*ri0, o[nt][1]*ri0);
            *(float2*)&out[((size_t)bh*SEQ + s0 + r1)*HD + cb] =
                make_float2(o[nt][2]*ri1, o[nt][3]*ri1);
        }
        __syncthreads();
        if (tt + 2 < NTF) {
            int sn = (blockIdx.x*NTF + tt + 2)*TS;
            const float* Qb = Q + ((size_t)bh*SEQ + sn)*HD;
            #pragma unroll
            for (int i = 0; i < 4; i++) {
                int e4 = tid + i*256;
                int r = e4 >> 4, c = (e4 & 15) << 2;
                cpa16(smem_u32(&sQ[r*PA + c]), Qb + r*HD + c);
            }
            if (tid < 16) cpa16(smem_u32(&smk[buf][tid*4]),
                                mask + (size_t)b*SEQ + sn + tid*4);
            cp_commit();
        }
    }
}

// ================= launch =================
extern "C" void kernel_launch(void* const* d_in, const int* in_sizes, int n_in,
                              void* d_out, int out_size) {
    const float* Q    = (const float*)d_in[0];
    const float* K    = (const float*)d_in[1];
    const float* V    = (const float*)d_in[2];
    const float* mask = (const float*)d_in[3];
    float* out = (float*)d_out;

    const int SMEM_MID = (4 * NL * PA + 2 * NL * PB) * sizeof(float);  // 106496
    const int SMEM_FIN = (4 * NL * PA + NL * PB) * sizeof(float);      // 88064
    cudaFuncSetAttribute(k_mid,   cudaFuncAttributeMaxDynamicSharedMemorySize, SMEM_MID);
    cudaFuncSetAttribute(k_final, cudaFuncAttributeMaxDynamicSharedMemorySize, SMEM_FIN);

    k_landmarks<<<dim3(NL, BH), 256>>>(Q, K, mask);
    k_kernel2<<<BH, NL>>>();
    k_mid<<<dim3(NSPLIT + 1, BH), 256, SMEM_MID>>>(K, V, mask);
    k_mergewmat<<<BH, 256>>>();
    k_final<<<dim3(SEQ/TS/NTF, BH), 256, SMEM_FIN>>>(Q, mask, out);
}

// round 14
// speedup vs baseline: 1.9012x; 1.0043x over previous
#include <cuda_runtime.h>
#include <math.h>
#include <stdint.h>

#define BATCHN 8
#define NHEAD 12
#define BH 96            // BATCHN*NHEAD
#define SEQ 4096
#define HD 64
#define NL 64            // landmarks
#define SEG 64           // SEQ / NL
#define NSPLIT 8
#define SPLEN 512        // SEQ / NSPLIT
#define TS 64
#define NTF 4            // seq tiles per k_final block
#define SCALE 0.35355339059327373f   // 64^(-1/4)
#define NEGBIG 1000000000.0f
#define PA 68            // pitch for n-row-indexed mma buffers (== 4 mod 32, 16B rows)
#define PB 72            // pitch for k-row-indexed mma buffers (== 8 mod 32, 16B rows)
#define PI 65            // pitch for SIMT 64x64 matmuls (scalar access only!)
#define PT 68
#define P2 65

// -------- scratch --------
__device__ float g_Ql[BH*NL*HD];
__device__ float g_Kl[BH*NL*HD];
__device__ float g_K2[BH*NL*NL];
__device__ float g_colmax[BH];
__device__ float g_Inv[BH*NL*NL];
__device__ float g_pacc[BH*NSPLIT*NL*HD];
__device__ float g_pd[BH*NSPLIT*NL];
__device__ float g_W[BH*NL*HD];

__device__ __forceinline__ float tf32r(float x){
    uint32_t u; asm("cvt.rna.tf32.f32 %0, %1;" : "=r"(u) : "f"(x));
    return __uint_as_float(u);
}
__device__ __forceinline__ uint32_t tf32u(float x){
    uint32_t u; asm("cvt.rna.tf32.f32 %0, %1;" : "=r"(u) : "f"(x));
    return u;
}
__device__ __forceinline__ void mma8(float c[4],
                                     uint32_t a0,uint32_t a1,uint32_t a2,uint32_t a3,
                                     uint32_t b0,uint32_t b1){
    asm volatile("mma.sync.aligned.m16n8k8.row.col.f32.tf32.tf32.f32 "
        "{%0,%1,%2,%3}, {%4,%5,%6,%7}, {%8,%9}, {%0,%1,%2,%3};"
        : "+f"(c[0]),"+f"(c[1]),"+f"(c[2]),"+f"(c[3])
        : "r"(a0),"r"(a1),"r"(a2),"r"(a3),"r"(b0),"r"(b1));
}
__device__ __forceinline__ uint32_t smem_u32(const void* p){
    return (uint32_t)__cvta_generic_to_shared(p);
}
__device__ __forceinline__ void cpa16(uint32_t d, const void* s){
    asm volatile("cp.async.cg.shared.global [%0], [%1], 16;" :: "r"(d), "l"(s));
}
__device__ __forceinline__ void cp_commit(){ asm volatile("cp.async.commit_group;"); }
template<int N> __device__ __forceinline__ void cp_wait(){
    asm volatile("cp.async.wait_group %0;" :: "n"(N));
}
__device__ __forceinline__ void bar_pair(int id){
    asm volatile("bar.sync %0, 64;" :: "r"(id) : "memory");
}

// ================= K1: landmarks (float4, 16-deep MLP) =================
__global__ void __launch_bounds__(256) k_landmarks(const float* __restrict__ Q,
                                                   const float* __restrict__ K,
                                                   const float* __restrict__ mask) {
    int bh = blockIdx.y;
    int l  = blockIdx.x;
    int b  = bh / NHEAD;
    int t  = threadIdx.x;
    int c4 = (t & 15) << 2;
    int rg = t >> 4;                 // 16 row groups of 4 rows
    __shared__ float redQ[16][68];
    __shared__ float redK[16][68];
    const float* qb = Q + ((size_t)bh*SEQ + l*SEG)*HD;
    const float* kb = K + ((size_t)bh*SEQ + l*SEG)*HD;
    const float* mr = mask + (size_t)b*SEQ + l*SEG;
    float sq0=0.f,sq1=0.f,sq2=0.f,sq3=0.f;
    float sk0=0.f,sk1=0.f,sk2=0.f,sk3=0.f;
    #pragma unroll
    for (int k = 0; k < 4; k++) {
        int r = rg + k*16;
        float m = mr[r];
        float4 q = *(const float4*)(qb + r*HD + c4);
        float4 kk = *(const float4*)(kb + r*HD + c4);
        sq0 += q.x*m; sq1 += q.y*m; sq2 += q.z*m; sq3 += q.w*m;
        sk0 += kk.x*m; sk1 += kk.y*m; sk2 += kk.z*m; sk3 += kk.w*m;
    }
    *(float4*)&redQ[rg][c4] = make_float4(sq0,sq1,sq2,sq3);
    *(float4*)&redK[rg][c4] = make_float4(sk0,sk1,sk2,sk3);
    __syncthreads();
    if (t < NL) {
        float aq = 0.f, ak = 0.f;
        #pragma unroll
        for (int g = 0; g < 16; g++) { aq += redQ[g][t]; ak += redK[g][t]; }
        float cc = SCALE / (float)SEG;
        g_Ql[(bh*NL + l)*HD + t] = aq * cc;
        g_Kl[(bh*NL + l)*HD + t] = ak * cc;
    }
}

// ================= K2a: kernel_2 softmax + colsum max =================
__global__ void k_kernel2(void) {
    int bh = blockIdx.x;
    int t  = threadIdx.x;   // 64 threads
    __shared__ float sQ[NL*P2];
    __shared__ float sK[NL*P2];
    __shared__ float sP[NL*P2];
    __shared__ float red[NL];
    for (int r = 0; r < NL; r++) {
        sQ[r*P2 + t] = g_Ql[(bh*NL + r)*HD + t];
        sK[r*P2 + t] = g_Kl[(bh*NL + r)*HD + t];
    }
    __syncthreads();
    int l = t;
    float mx = -1e30f;
    for (int m = 0; m < NL; m++) {
        float s = 0.f;
        #pragma unroll 8
        for (int k = 0; k < HD; k++) s += sQ[l*P2 + k] * sK[m*P2 + k];
        sP[l*P2 + m] = s;
        mx = fmaxf(mx, s);
    }
    float sum = 0.f;
    for (int m = 0; m < NL; m++) {
        float e = __expf(sP[l*P2 + m] - mx);
        sP[l*P2 + m] = e;
        sum += e;
    }
    float inv = 1.f / sum;
    for (int m = 0; m < NL; m++) {
        float v = sP[l*P2 + m] * inv;
        sP[l*P2 + m] = v;
        g_K2[(bh*NL + l)*NL + m] = v;
    }
    __syncthreads();
    float cs = 0.f;
    for (int r = 0; r < NL; r++) cs += sP[r*P2 + t];
    red[t] = cs;
    __syncthreads();
    for (int s = 32; s > 0; s >>= 1) {
        if (t < s) red[t] = fmaxf(red[t], red[t + s]);
        __syncthreads();
    }
    if (t == 0) g_colmax[bh] = red[0];
}

// ===== 64x64 SIMT matmul: C = alpha * A @ (beta*I + gamma*B); C may alias A or B =====
template<int P>
__device__ __forceinline__ void mm64(float* C, const float* A, const float* B,
                                     float beta, float gamma, float alpha, int tid) {
    int i0 = (tid >> 4) << 2;
    int j0 = (tid & 15) << 2;
    float acc[4][4];
    #pragma unroll
    for (int u = 0; u < 4; u++)
        #pragma unroll
        for (int v = 0; v < 4; v++) acc[u][v] = 0.f;
    for (int k = 0; k < HD; k++) {
        float a[4], b[4];
        #pragma unroll
        for (int u = 0; u < 4; u++) a[u] = A[(i0+u)*P + k];
        #pragma unroll
        for (int v = 0; v < 4; v++) {
            float x = B[k*P + j0 + v];
            b[v] = gamma * x + ((k == j0 + v) ? beta : 0.f);
        }
        #pragma unroll
        for (int u = 0; u < 4; u++)
            #pragma unroll
            for (int v = 0; v < 4; v++) acc[u][v] += a[u] * b[v];
    }
    __syncthreads();
    #pragma unroll
    for (int u = 0; u < 4; u++)
        #pragma unroll
        for (int v = 0; v < 4; v++) C[(i0+u)*P + j0 + v] = alpha * acc[u][v];
    __syncthreads();
}

// ================= Newton-Schulz pinv body (fp32 SIMT, 4 buffers) =================
__device__ void inv_body(float* sm) {
    float* Km = sm;
    float* Vb = sm + 1*NL*PI;
    float* Pb = sm + 2*NL*PI;
    float* T1 = sm + 3*NL*PI;
    int bh = blockIdx.y;
    int tid = threadIdx.x;
    for (int e = tid; e < NL*NL; e += 256) {
        int r = e >> 6, c = e & 63;
        Km[r*PI + c] = g_K2[bh*NL*NL + e];
    }
    float gmax = -1e30f;
    for (int i = 0; i < BH; i++) gmax = fmaxf(gmax, g_colmax[i]);
    float ig = 1.f / gmax;
    __syncthreads();
    for (int e = tid; e < NL*NL; e += 256) {
        int r = e >> 6, c = e & 63;
        Vb[r*PI + c] = Km[c*PI + r] * ig;
    }
    __syncthreads();
    float *Vp = Vb, *Tp = T1;
    for (int it = 0; it < 6; it++) {
        mm64<PI>(Pb, Km, Vp, 0.f,  1.f, 1.f,   tid);
        mm64<PI>(Tp, Pb, Pb, 7.f, -1.f, 1.f,   tid);
        mm64<PI>(Pb, Pb, Tp, 15.f,-1.f, 1.f,   tid);
        mm64<PI>(Tp, Vp, Pb, 13.f,-1.f, 0.25f, tid);
        float* t = Vp; Vp = Tp; Tp = t;
    }
    for (int e = tid; e < NL*NL; e += 256) {
        int r = e >> 6, c = e & 63;
        g_Inv[bh*NL*NL + e] = Vp[r*PI + c];
    }
}

// ====== flash3 prefetch: raw K/V tiles + mask tile via cp.async ======
__device__ __forceinline__ void f3_prefetch(const float* K, const float* V,
                                            const float* mask, float* sKb, float* sVb,
                                            float* smaskb, int bh, int b, int s0, int tid){
    const float* Kb = K + ((size_t)bh*SEQ + s0)*HD;
    const float* Vb = V + ((size_t)bh*SEQ + s0)*HD;
    #pragma unroll
    for (int i = 0; i < 4; i++) {
        int e4 = tid + i*256;
        int r = e4 >> 4, c = (e4 & 15) << 2;
        cpa16(smem_u32(&sKb[r*PA + c]), Kb + r*HD + c);
        cpa16(smem_u32(&sVb[r*PB + c]), Vb + r*HD + c);
    }
    if (tid < 16) cpa16(smem_u32(&smaskb[tid*4]), mask + (size_t)b*SEQ + s0 + tid*4);
}

// ====== flash kernel_3 @ V body: Q fragments in regs, pair-barrier P exchange ======
__device__ void flash3_body(const float* __restrict__ K, const float* __restrict__ V,
                            const float* __restrict__ mask, float* sm) {
    float* sP  = sm;                      // 64 x PA  (Q staging, then P buffer)
    float* sK0 = sm + NL*PA;              // 64 x PA  raw K tiles
    float* sK1 = sm + 2*NL*PA;
    float* sV0 = sm + 3*NL*PA;            // 64 x PB  raw V tiles
    float* sV1 = sm + 3*NL*PA + NL*PB;
    __shared__ float smask[2][TS];
    __shared__ float dred[NL][2];

    int bh = blockIdx.y, sp = blockIdx.x, b = bh / NHEAD;
    int tid = threadIdx.x, lane = tid & 31, warp = tid >> 5;
    int wr = warp & 3, wc = warp >> 2;
    int g = lane >> 2, t4 = lane & 3;
    int r0 = wr*16 + g, r1 = r0 + 8;

    // prefetch tiles 0,1
    f3_prefetch(K, V, mask, sK0, sV0, smask[0], bh, b, sp*SPLEN + 0*TS, tid); cp_commit();
    f3_prefetch(K, V, mask, sK1, sV1, smask[1], bh, b, sp*SPLEN + 1*TS, tid); cp_commit();

    // stage rna(Ql*SCALE) into sP, pull A-fragments into registers, then recycle sP as P
    for (int e4 = tid; e4 < NL*HD/4; e4 += 256) {
        int r = e4 >> 4, c = (e4 & 15) << 2;
        float4 q = *(const float4*)&g_Ql[(size_t)bh*NL*HD + r*HD + c];
        *(float4*)&sP[r*PA + c] = make_float4(tf32r(q.x*SCALE), tf32r(q.y*SCALE),
                                              tf32r(q.z*SCALE), tf32r(q.w*SCALE));
    }
    __syncthreads();
    uint32_t qa[8][4];
    #pragma unroll
    for (int ks = 0; ks < 8; ks++) {
        int kb = ks*8 + t4;
        qa[ks][0] = __float_as_uint(sP[r0*PA + kb]);
        qa[ks][1] = __float_as_uint(sP[r1*PA + kb]);
        qa[ks][2] = __float_as_uint(sP[r0*PA + kb + 4]);
        qa[ks][3] = __float_as_uint(sP[r1*PA + kb + 4]);
    }

    float o[4][4];
    #pragma unroll
    for (int nt = 0; nt < 4; nt++)
        #pragma unroll
        for (int j = 0; j < 4; j++) o[nt][j] = 0.f;
    float dp0 = 0.f, dp1 = 0.f;

    for (int tt = 0; tt < SPLEN/TS; tt++) {
        int buf = tt & 1;
        float* sK = buf ? sK1 : sK0;
        float* sV = buf ? sV1 : sV0;
        cp_wait<1>();
        __syncthreads();   // K/V/mask tile ready; prior-tile P@V reads done

        // S = Ql @ Ks^T  per n-tile (cf[4] live), exp + stage P immediately
        #pragma unroll
        for (int nt = 0; nt < 4; nt++) {
            float cf[4] = {0.f, 0.f, 0.f, 0.f};
            int n = wc*32 + nt*8 + g;
            #pragma unroll
            for (int ks = 0; ks < 8; ks++) {
                int kb = ks*8 + t4;
                uint32_t b0 = tf32u(sK[n*PA + kb]);
                uint32_t b1 = tf32u(sK[n*PA + kb + 4]);
                mma8(cf, qa[ks][0], qa[ks][1], qa[ks][2], qa[ks][3], b0, b1);
            }
            int cb = wc*32 + nt*8 + t4*2;
            float bb0 = -NEGBIG * (1.f - smask[buf][cb]);
            float bb1 = -NEGBIG * (1.f - smask[buf][cb+1]);
            float e0 = __expf(cf[0] + bb0), e1 = __expf(cf[1] + bb1);
            float e2 = __expf(cf[2] + bb0), e3 = __expf(cf[3] + bb1);
            dp0 += e0 + e1; dp1 += e2 + e3;
            *(float2*)&sP[r0*PA + cb] = make_float2(tf32r(e0), tf32r(e1));
            *(float2*)&sP[r1*PA + cb] = make_float2(tf32r(e2), tf32r(e3));
        }
        bar_pair(wr + 1);   // pair-only: this band's P complete (wc halves)

        // O += P @ V
        #pragma unroll
        for (int ks = 0; ks < 8; ks++) {
            int kb = ks*8 + t4;
            uint32_t a0 = __float_as_uint(sP[r0*PA + kb]);
            uint32_t a1 = __float_as_uint(sP[r1*PA + kb]);
            uint32_t a2 = __float_as_uint(sP[r0*PA + kb + 4]);
            uint32_t a3 = __float_as_uint(sP[r1*PA + kb + 4]);
            #pragma unroll
            for (int nt = 0; nt < 4; nt++) {
                int n = wc*32 + nt*8 + g;
                uint32_t b0 = tf32u(sV[kb*PB + n]);
                uint32_t b1 = tf32u(sV[(kb+4)*PB + n]);
                mma8(o[nt], a0, a1, a2, a3, b0, b1);
            }
        }
        __syncthreads();   // all K/V reads done before overwrite
        if (tt + 2 < SPLEN/TS) {
            f3_prefetch(K, V, mask, sK, sV, smask[buf], bh, b,
                        sp*SPLEN + (tt+2)*TS, tid);
            cp_commit();
        }
    }
    size_t base = ((size_t)bh*NSPLIT + sp)*NL;
    #pragma unroll
    for (int nt = 0; nt < 4; nt++) {
        int cb = wc*32 + nt*8 + t4*2;
        *(float2*)&g_pacc[(base + r0)*HD + cb] = make_float2(o[nt][0], o[nt][1]);
        *(float2*)&g_pacc[(base + r1)*HD + cb] = make_float2(o[nt][2], o[nt][3]);
    }
    dp0 += __shfl_xor_sync(0xffffffffu, dp0, 1);
    dp0 += __shfl_xor_sync(0xffffffffu, dp0, 2);
    dp1 += __shfl_xor_sync(0xffffffffu, dp1, 1);
    dp1 += __shfl_xor_sync(0xffffffffu, dp1, 2);
    if (t4 == 0) { dred[r0][wc] = dp0; dred[r1][wc] = dp1; }
    __syncthreads();
    if (tid < NL) g_pd[base + tid] = dred[tid][0] + dred[tid][1];
}

// ================= fused middle kernel: flash3 (x<8) || inv (x==8) =================
__global__ void __launch_bounds__(256, 2) k_mid(const float* __restrict__ K,
                                                const float* __restrict__ V,
                                                const float* __restrict__ mask) {
    extern __shared__ float sm[];
    if (blockIdx.x < NSPLIT) flash3_body(K, V, mask, sm);
    else                     inv_body(sm);
}

// ================= merge partials + W = Inv @ T3V =================
__global__ void __launch_bounds__(256) k_mergewmat(void) {
    __shared__ float A[NL*PI];
    __shared__ float T[NL*PT];
    __shared__ float dtot[NL];
    int bh = blockIdx.x, tid = threadIdx.x;
    for (int e = tid; e < NL*NL; e += 256) {
        int r = e >> 6, c = e & 63;
        A[r*PI + c] = g_Inv[bh*NL*NL + e];
    }
    if (tid < NL) {
        float s = 0.f;
        #pragma unroll
        for (int k = 0; k < NSPLIT; k++) s += g_pd[((size_t)bh*NSPLIT + k)*NL + tid];
        dtot[tid] = s;
    }
    __syncthreads();
    for (int e4 = tid; e4 < NL*HD/4; e4 += 256) {
        int r = e4 >> 4, c = (e4 & 15) << 2;
        float4 acc = make_float4(0.f, 0.f, 0.f, 0.f);
        #pragma unroll
        for (int s = 0; s < NSPLIT; s++) {
            float4 p = *(const float4*)&g_pacc[(((size_t)bh*NSPLIT + s)*NL + r)*HD + c];
            acc.x += p.x; acc.y += p.y; acc.z += p.z; acc.w += p.w;
        }
        float id = 1.f / dtot[r];
        *(float4*)&T[r*PT + c] = make_float4(acc.x*id, acc.y*id, acc.z*id, acc.w*id);
    }
    __syncthreads();
    int i0 = (tid >> 4) << 2;
    int j0 = (tid & 15) << 2;
    float acc[4][4];
    #pragma unroll
    for (int u = 0; u < 4; u++)
        #pragma unroll
        for (int v = 0; v < 4; v++) acc[u][v] = 0.f;
    for (int k = 0; k < NL; k++) {
        float a[4], b[4];
        #pragma unroll
        for (int u = 0; u < 4; u++) a[u] = A[(i0+u)*PI + k];
        #pragma unroll
        for (int v = 0; v < 4; v++) b[v] = T[k*PT + j0 + v];
        #pragma unroll
        for (int u = 0; u < 4; u++)
            #pragma unroll
            for (int v = 0; v < 4; v++) acc[u][v] += a[u] * b[v];
    }
    #pragma unroll
    for (int u = 0; u < 4; u++)
        #pragma unroll
        for (int v = 0; v < 4; v++)
            g_W[((size_t)bh*NL + i0 + u)*HD + j0 + v] = acc[u][v];
}

// ===== K5: X = softmax(Qs K_l^T) @ W — 3 blocks/SM, sP aliased onto consumed sQ =====
__global__ void __launch_bounds__(256, 3) k_final(const float* __restrict__ Q,
                                                  const float* __restrict__ mask,
                                                  float* __restrict__ out) {
    extern __shared__ float sm[];
    float* sKl = sm;                     // 64 x PA  (rounded at staging)
    float* sQ0 = sm + NL*PA;             // 64 x PA  raw Q / then P (band-aliased)
    float* sQ1 = sm + 2*NL*PA;
    float* sW  = sm + 3*NL*PA;           // 64 x PB  (rounded at staging)
    __shared__ float smk[2][TS];
    __shared__ float rsum[NL][2];

    int bh = blockIdx.y, b = bh / NHEAD;
    int tid = threadIdx.x, lane = tid & 31, warp = tid >> 5;
    int wr = warp & 3, wc = warp >> 2;
    int g = lane >> 2, t4 = lane & 3;
    int r0 = wr*16 + g, r1 = r0 + 8;

    // prefetch Q tiles 0,1 (raw) + mask
    #pragma unroll
    for (int p = 0; p < 2; p++) {
        int s0 = (blockIdx.x*NTF + p)*TS;
        const float* Qb = Q + ((size_t)bh*SEQ + s0)*HD;
        float* dst = p ? sQ1 : sQ0;
        #pragma unroll
        for (int i = 0; i < 4; i++) {
            int e4 = tid + i*256;
            int r = e4 >> 4, c = (e4 & 15) << 2;
            cpa16(smem_u32(&dst[r*PA + c]), Qb + r*HD + c);
        }
        if (tid < 16) cpa16(smem_u32(&smk[p][tid*4]), mask + (size_t)b*SEQ + s0 + tid*4);
        cp_commit();
    }

    for (int e4 = tid; e4 < NL*HD/4; e4 += 256) {
        int r = e4 >> 4, c = (e4 & 15) << 2;
        float4 kl = *(const float4*)&g_Kl[(size_t)bh*NL*HD + r*HD + c];
        float4 w  = *(const float4*)&g_W[(size_t)bh*NL*HD + r*HD + c];
        *(float4*)&sKl[r*PA + c] = make_float4(tf32r(kl.x), tf32r(kl.y), tf32r(kl.z), tf32r(kl.w));
        *(float4*)&sW[r*PB + c]  = make_float4(tf32r(w.x), tf32r(w.y), tf32r(w.z), tf32r(w.w));
    }

    for (int tt = 0; tt < NTF; tt++) {
        int buf = tt & 1;
        float* sQ = buf ? sQ1 : sQ0;     // raw Q tile; becomes P after pair barrier
        cp_wait<1>();
        __syncthreads();                  // Q tile ready (+ sKl/sW on tt=0)

        // pull this band's Q fragments (RNA-rounded) into regs, then free the band for P
        uint32_t qa[8][4];
        #pragma unroll
        for (int ks = 0; ks < 8; ks++) {
            int kb = ks*8 + t4;
            qa[ks][0] = tf32u(sQ[r0*PA + kb]);
            qa[ks][1] = tf32u(sQ[r1*PA + kb]);
            qa[ks][2] = tf32u(sQ[r0*PA + kb + 4]);
            qa[ks][3] = tf32u(sQ[r1*PA + kb + 4]);
        }
        bar_pair(wr + 1);                 // pair done reading its Q band

        float f0 = smk[buf][r0] * SCALE;
        float f1 = smk[buf][r1] * SCALE;
        float dp0 = 0.f, dp1 = 0.f;
        #pragma unroll
        for (int nt = 0; nt < 4; nt++) {
            float cf[4] = {0.f, 0.f, 0.f, 0.f};
            int n = wc*32 + nt*8 + g;
            #pragma unroll
            for (int ks = 0; ks < 8; ks++) {
                int kb = ks*8 + t4;
                uint32_t b0 = __float_as_uint(sKl[n*PA + kb]);
                uint32_t b1 = __float_as_uint(sKl[n*PA + kb + 4]);
                mma8(cf, qa[ks][0], qa[ks][1], qa[ks][2], qa[ks][3], b0, b1);
            }
            int cb = wc*32 + nt*8 + t4*2;
            float e0 = __expf(cf[0]*f0), e1 = __expf(cf[1]*f0);
            float e2 = __expf(cf[2]*f1), e3 = __expf(cf[3]*f1);
            dp0 += e0 + e1; dp1 += e2 + e3;
            *(float2*)&sQ[r0*PA + cb] = make_float2(tf32r(e0), tf32r(e1));
            *(float2*)&sQ[r1*PA + cb] = make_float2(tf32r(e2), tf32r(e3));
        }
        dp0 += __shfl_xor_sync(0xffffffffu, dp0, 1);
        dp0 += __shfl_xor_sync(0xffffffffu, dp0, 2);
        dp1 += __shfl_xor_sync(0xffffffffu, dp1, 1);
        dp1 += __shfl_xor_sync(0xffffffffu, dp1, 2);
        if (t4 == 0) { rsum[r0][wc] = dp0; rsum[r1][wc] = dp1; }
        bar_pair(wr + 1);                 // pair: P band + rsum visible

        float o[4][4];
        #pragma unroll
        for (int nt = 0; nt < 4; nt++)
            #pragma unroll
            for (int j = 0; j < 4; j++) o[nt][j] = 0.f;
        #pragma unroll
        for (int ks = 0; ks < 8; ks++) {
            int kb = ks*8 + t4;
            uint32_t a0 = __float_as_uint(sQ[r0*PA + kb]);
            uint32_t a1 = __float_as_uint(sQ[r1*PA + kb]);
            uint32_t a2 = __float_as_uint(sQ[r0*PA + kb + 4]);
            uint32_t a3 = __float_as_uint(sQ[r1*PA + kb + 4]);
            #pragma unroll
            for (int nt = 0; nt < 4; nt++) {
                int n = wc*32 + nt*8 + g;
                uint32_t b0 = __float_as_uint(sW[kb*PB + n]);
                uint32_t b1 = __float_as_uint(sW[(kb+4)*PB + n]);
                mma8(o[nt], a0, a1, a2, a3, b0, b1);
            }
        }
        int s0 = (blockIdx.x*NTF + tt)*TS;
        float ri0 = 1.f / (rsum[r0][0] + rsum[r0][1]);
        float ri1 = 1.f / (rsum[r1][0] + rsum[r1][1]);
        #pragma unroll
        for (int nt = 0; nt < 4; nt++) {
            int cb = wc*32 + nt*8 + t4*2;
            *(float2*)&out[((size_t)bh*SEQ + s0 + r0)*HD + cb] =
                make_float2(o[nt][0]*ri0, o[nt][1]*ri0);
            *(float2*)&out[((size_t)bh*SEQ + s0 + r1)*HD + cb] =
                make_float2(o[nt][2]*ri1, o[nt][3]*ri1);
        }
        __syncthreads();                  // all bands' P reads done before overwrite
        if (tt + 2 < NTF) {
            int sn = (blockIdx.x*NTF + tt + 2)*TS;
            const float* Qb = Q + ((size_t)bh*SEQ + sn)*HD;
            #pragma unroll
            for (int i = 0; i < 4; i++) {
                int e4 = tid + i*256;
                int r = e4 >> 4, c = (e4 & 15) << 2;
                cpa16(smem_u32(&sQ[r*PA + c]), Qb + r*HD + c);
            }
            if (tid < 16) cpa16(smem_u32(&smk[buf][tid*4]),
                                mask + (size_t)b*SEQ + sn + tid*4);
            cp_commit();
        }
    }
}

// ================= launch =================
extern "C" void kernel_launch(void* const* d_in, const int* in_sizes, int n_in,
                              void* d_out, int out_size) {
    const float* Q    = (const float*)d_in[0];
    const float* K    = (const float*)d_in[1];
    const float* V    = (const float*)d_in[2];
    const float* mask = (const float*)d_in[3];
    float* out = (float*)d_out;

    const int SMEM_MID = (3 * NL * PA + 2 * NL * PB) * sizeof(float);  // 89088
    const int SMEM_FIN = (3 * NL * PA + NL * PB) * sizeof(float);      // 70656
    cudaFuncSetAttribute(k_mid,   cudaFuncAttributeMaxDynamicSharedMemorySize, SMEM_MID);
    cudaFuncSetAttribute(k_final, cudaFuncAttributeMaxDynamicSharedMemorySize, SMEM_FIN);

    k_landmarks<<<dim3(NL, BH), 256>>>(Q, K, mask);
    k_kernel2<<<BH, NL>>>();
    k_mid<<<dim3(NSPLIT + 1, BH), 256, SMEM_MID>>>(K, V, mask);
    k_mergewmat<<<BH, 256>>>();
    k_final<<<dim3(SEQ/TS/NTF, BH), 256, SMEM_FIN>>>(Q, mask, out);
}